// round 11
// baseline (speedup 1.0000x reference)
#include <cuda_runtime.h>
#include <cuda_bf16.h>
#include <cuda.h>
#include <stdint.h>

#define NN 4096
#define DD 256
#define MARGIN 0.1f
#define EPS 0.002f
#define MAXTIES 65536

#if defined(__CUDA_ARCH_FEAT_SM103_ALL) || defined(__CUDA_ARCH_FEAT_SM100_ALL)
#define HAS_TCGEN05 1
#else
#define HAS_TCGEN05 0
#endif

// idesc kind::f16: dtype=F32, atype=btype=BF16, N=256, M=128 (cg1)
#define IDESC 0x08400490u

// tile geometry
#define TM 128
#define TN 256
#define TILES_X (NN / TN)            // 16
#define TILES_Y (NN / TM)            // 32
#define NTILES  (TILES_X * TILES_Y)  // 512
#define NCTA    148
#define NTHREADS 320                 // 8 epilogue warps + MMA warp + TMA warp

// chunk = K=32 (64B rows, SW64). stage: Ahi 8K | Alo 8K | Bhi 16K | Blo 16K
#define ST_ALO   8192
#define ST_BHI   16384
#define ST_BLO   32768
#define ST_BYTES 49152
#define NSTAGE   4
#define CHUNKS_PER_TILE 8            // 256 / 32

#define OFF_TMEMP  (NSTAGE * ST_BYTES)       // 196608
#define OFF_MB     (OFF_TMEMP + 16)
#define MB_FULL_O  0                          // 4 x 8B
#define MB_EMPT_O  32                         // 4 x 8B
#define MB_RES_O   64                         // 2 x 8B
#define MB_EPI_O   80                         // 2 x 8B
#define OFF_DC     (OFF_TMEMP + 128)          // 2 x 256 floats
#define SMEM_DYN   (OFF_DC + 2048 + 1024)

typedef unsigned long long u64;

// ---- device-global scratch ----
__device__ double g_vt_sum;
__device__ double g_tv_sum;
__device__ unsigned g_done;
__device__ unsigned g_ntie;
__device__ unsigned g_tie[MAXTIES];
__device__ int    g_cnt[NN];
__device__ float  g_diag[NN];
__device__ __align__(1024) __nv_bfloat16 g_Vhi[NN * DD];
__device__ __align__(1024) __nv_bfloat16 g_Vlo[NN * DD];
__device__ __align__(1024) __nv_bfloat16 g_Thi[NN * DD];
__device__ __align__(1024) __nv_bfloat16 g_Tlo[NN * DD];

// ======================= PTX helpers =======================
__device__ __forceinline__ uint32_t smem_u32(const void* p) {
    uint32_t a;
    asm("{ .reg .u64 t; cvta.to.shared.u64 t, %1; cvt.u32.u64 %0, t; }"
        : "=r"(a) : "l"(p));
    return a;
}

#define MBARRIER_INIT(addr, cnt) \
    asm volatile("mbarrier.init.shared.b64 [%0], %1;" \
        :: "r"((uint32_t)(addr)), "r"((uint32_t)(cnt)) : "memory")

#define MBARRIER_EXPECT_TX(addr, bytes) \
    asm volatile("mbarrier.arrive.expect_tx.shared.b64 _, [%0], %1;" \
        :: "r"((uint32_t)(addr)), "r"((uint32_t)(bytes)) : "memory")

#define MBARRIER_ARRIVE(addr) \
    asm volatile("mbarrier.arrive.shared.b64 _, [%0];" \
        :: "r"((uint32_t)(addr)) : "memory")

#define MBARRIER_WAIT_PARITY(addr, parity) do {                                   \
    uint32_t _mb = (uint32_t)(addr);                                              \
    uint32_t _ph = (uint32_t)(parity);                                            \
    uint32_t _done;                                                               \
    asm volatile("{\n\t.reg .pred p;\n\t"                                         \
        "mbarrier.try_wait.parity.acquire.cta.shared::cta.b64 p, [%1], %2;\n\t"   \
        "selp.b32 %0, 1, 0, p;\n\t}"                                              \
        : "=r"(_done) : "r"(_mb), "r"(_ph) : "memory");                           \
    if (!_done) {                                                                 \
        asm volatile("{\n\t.reg .pred P1;\n\t"                                    \
            "W_%=:\n\t"                                                           \
            "mbarrier.try_wait.parity.acquire.cta.shared::cta.b64 P1, [%0], %1, 0x989680;\n\t" \
            "@P1 bra.uni D_%=;\n\t"                                               \
            "bra.uni W_%=;\n\t"                                                   \
            "D_%=:\n\t}"                                                          \
            :: "r"(_mb), "r"(_ph) : "memory");                                    \
    }                                                                             \
} while (0)

#if HAS_TCGEN05
#define TCGEN05_ALLOC(res_addr, ncols) \
    asm volatile("tcgen05.alloc.cta_group::1.sync.aligned.shared::cta.b32 [%0], %1;" \
        :: "r"((uint32_t)(res_addr)), "r"((uint32_t)(ncols)) : "memory")
#define TCGEN05_RELINQ() \
    asm volatile("tcgen05.relinquish_alloc_permit.cta_group::1.sync.aligned;")
#define TCGEN05_DEALLOC(tmem, ncols) \
    asm volatile("tcgen05.dealloc.cta_group::1.sync.aligned.b32 %0, %1;" \
        :: "r"(tmem), "r"((uint32_t)(ncols)))
#define TCGEN05_COMMIT(mbar) \
    asm volatile("tcgen05.commit.cta_group::1.mbarrier::arrive::one.shared::cluster.b64 [%0];" \
        :: "r"((uint32_t)(mbar)) : "memory")
#define TCGEN05_FENCE_AFTER() \
    asm volatile("tcgen05.fence::after_thread_sync;" ::: "memory")
#define TCGEN05_FENCE_BEFORE() \
    asm volatile("tcgen05.fence::before_thread_sync;" ::: "memory")
#define TCGEN05_WAIT_LD() \
    asm volatile("tcgen05.wait::ld.sync.aligned;" ::: "memory")

#define TCGEN05_LD_X32(r, addr) \
    asm volatile("tcgen05.ld.sync.aligned.32x32b.x32.b32 " \
        "{%0, %1, %2, %3, %4, %5, %6, %7, %8, %9, %10, %11, %12, %13, %14, %15, " \
        " %16, %17, %18, %19, %20, %21, %22, %23, %24, %25, %26, %27, %28, %29, %30, %31}, [%32];" \
        : "=r"((r)[0]),  "=r"((r)[1]),  "=r"((r)[2]),  "=r"((r)[3]),  \
          "=r"((r)[4]),  "=r"((r)[5]),  "=r"((r)[6]),  "=r"((r)[7]),  \
          "=r"((r)[8]),  "=r"((r)[9]),  "=r"((r)[10]), "=r"((r)[11]), \
          "=r"((r)[12]), "=r"((r)[13]), "=r"((r)[14]), "=r"((r)[15]), \
          "=r"((r)[16]), "=r"((r)[17]), "=r"((r)[18]), "=r"((r)[19]), \
          "=r"((r)[20]), "=r"((r)[21]), "=r"((r)[22]), "=r"((r)[23]), \
          "=r"((r)[24]), "=r"((r)[25]), "=r"((r)[26]), "=r"((r)[27]), \
          "=r"((r)[28]), "=r"((r)[29]), "=r"((r)[30]), "=r"((r)[31]) \
        : "r"(addr))

// SW64 SMEM descriptor: layout=SW64(4), version=1, SBO=32, LBO=1
static __device__ __forceinline__ uint64_t make_desc64(uint32_t addr) {
    const uint64_t BASE =
        (uint64_t(4)  << 61) | (uint64_t(1) << 46) |
        (uint64_t(32) << 32) | (uint64_t(1) << 16);
    return BASE | ((uint64_t)(addr >> 4) & 0x3FFF);
}

__device__ __forceinline__ void tma_ld_2d(uint32_t dst, const void* map,
                                          int cx, int cy, uint32_t mbar) {
    asm volatile(
        "cp.async.bulk.tensor.2d.shared::cta.global.tile.mbarrier::complete_tx::bytes "
        "[%0], [%1, {%2, %3}], [%4];"
        :: "r"(dst), "l"(map), "r"(cx), "r"(cy), "r"(mbar) : "memory");
}

__device__ __forceinline__ void mma_f16_ss(uint32_t d, uint64_t da, uint64_t db,
                                           uint32_t en) {
    asm volatile("{\n\t.reg .pred p;\n\tsetp.ne.u32 p, %4, 0;\n\t"
        "tcgen05.mma.cta_group::1.kind::f16 [%0], %1, %2, %3, {%5, %5, %5, %5}, p;\n\t}"
        :: "r"(d), "l"(da), "l"(db), "r"(IDESC), "r"(en), "r"(0u) : "memory");
}
#endif  // HAS_TCGEN05

// ---------------------------------------------------------------------------
__device__ __forceinline__ void split4(float4 a, uint2& h, uint2& l) {
    __nv_bfloat162 hxy = __floats2bfloat162_rn(a.x, a.y);
    __nv_bfloat162 hzw = __floats2bfloat162_rn(a.z, a.w);
    float2 fxy = __bfloat1622float2(hxy);
    float2 fzw = __bfloat1622float2(hzw);
    __nv_bfloat162 lxy = __floats2bfloat162_rn(a.x - fxy.x, a.y - fxy.y);
    __nv_bfloat162 lzw = __floats2bfloat162_rn(a.z - fzw.x, a.w - fzw.y);
    h.x = reinterpret_cast<unsigned&>(hxy);
    h.y = reinterpret_cast<unsigned&>(hzw);
    l.x = reinterpret_cast<unsigned&>(lxy);
    l.y = reinterpret_cast<unsigned&>(lzw);
}

// exact fp32 dot of row r of V with row c of T (2-way ILP)
__device__ __forceinline__ float exact_dot(const float* __restrict__ V,
                                           const float* __restrict__ T,
                                           int r, int c) {
    const float4* a4 = reinterpret_cast<const float4*>(V + (size_t)r * DD);
    const float4* b4 = reinterpret_cast<const float4*>(T + (size_t)c * DD);
    float e0 = 0.f, e1 = 0.f;
    #pragma unroll 8
    for (int k = 0; k < DD / 4; k += 2) {
        float4 x = a4[k],      y = b4[k];
        float4 x1 = a4[k + 1], y1 = b4[k + 1];
        e0 += x.x * y.x + x.y * y.y + x.z * y.z + x.w * y.w;
        e1 += x1.x * y1.x + x1.y * y1.y + x1.z * y1.z + x1.w * y1.w;
    }
    return e0 + e1;
}

// ---------------------------------------------------------------------------
// Kernel 1: fused init — bf16 hi/lo split, exact fp32 diag, zero counters.
// ---------------------------------------------------------------------------
__global__ void init_kernel(const float* __restrict__ V,
                            const float* __restrict__ T) {
    const int gtid = blockIdx.x * blockDim.x + threadIdx.x;
    const int row  = gtid >> 5;
    const int lane = gtid & 31;
    if (gtid == 0) { g_vt_sum = 0.0; g_tv_sum = 0.0; g_done = 0u; g_ntie = 0u; }
    if (row >= NN) return;

    const float4* v4 = reinterpret_cast<const float4*>(V + (size_t)row * DD);
    const float4* t4 = reinterpret_cast<const float4*>(T + (size_t)row * DD);
    uint2* vh = reinterpret_cast<uint2*>(g_Vhi + (size_t)row * DD);
    uint2* vl = reinterpret_cast<uint2*>(g_Vlo + (size_t)row * DD);
    uint2* th = reinterpret_cast<uint2*>(g_Thi + (size_t)row * DD);
    uint2* tl = reinterpret_cast<uint2*>(g_Tlo + (size_t)row * DD);

    float acc = 0.f;
    #pragma unroll
    for (int p = 0; p < 2; p++) {
        const int idx = lane + p * 32;
        float4 a = v4[idx];
        float4 b = t4[idx];
        acc += a.x * b.x + a.y * b.y + a.z * b.z + a.w * b.w;
        uint2 h, l;
        split4(a, h, l); vh[idx] = h; vl[idx] = l;
        split4(b, h, l); th[idx] = h; tl[idx] = l;
    }
    #pragma unroll
    for (int off = 16; off > 0; off >>= 1)
        acc += __shfl_down_sync(0xFFFFFFFFu, acc, off);
    if (lane == 0) { g_diag[row] = acc; g_cnt[row] = 0; }
}

// ---------------------------------------------------------------------------
// Kernel 2: persistent warp-specialized tcgen05 GEMM, 4-stage TMA pipeline
// (K=32 chunks, SW64), decoupled MMA/TMA issuers, BRANCHLESS epilogue.
// 148 CTAs x 320 threads:
//   warps 0-7 : epilogue — warp w: rows (w&3)*32+lane, cols [(w>>2)*128,+128)
//   warp  8   : lane 0 = MMA issuer (also TMEM alloc)
//   warp  9   : lane 0 = TMA issuer
// Epilogue: hinges computed unconditionally (diagonal adds exactly MARGIN per
// direction, subtracted in finalize); rank count via diff>EPS; near-ties are
// pushed to a global list and resolved exactly by the last CTA.
// ---------------------------------------------------------------------------
__global__ __launch_bounds__(NTHREADS, 1)
void gemm_tc_kernel(const __grid_constant__ CUtensorMap mVhi,
                    const __grid_constant__ CUtensorMap mVlo,
                    const __grid_constant__ CUtensorMap mThi,
                    const __grid_constant__ CUtensorMap mTlo,
                    const float* __restrict__ V,
                    const float* __restrict__ T,
                    float* __restrict__ out) {
    extern __shared__ char smem_raw[];
    const uint32_t raw  = smem_u32(smem_raw);
    const uint32_t base = (raw + 1023) & ~1023u;
    char* gbase = smem_raw + (base - raw);

    const int tid  = threadIdx.x;
    const int lane = tid & 31;
    const int cta  = blockIdx.x;
    const int ntiles = (NTILES - cta + NCTA - 1) / NCTA;

    float vt = 0.f, tv = 0.f;

#if HAS_TCGEN05
    const int wid = tid >> 5;
    const uint32_t S_TMEMP = base + OFF_TMEMP;
    const uint32_t MB_FULL = base + OFF_MB + MB_FULL_O;  // 4 stages
    const uint32_t MB_EMPT = base + OFF_MB + MB_EMPT_O;  // 4 stages
    const uint32_t MB_RES  = base + OFF_MB + MB_RES_O;   // 2 bufs
    const uint32_t MB_EPI  = base + OFF_MB + MB_EPI_O;   // 2 bufs
    float* s_mdc = reinterpret_cast<float*>(gbase + OFF_DC);  // 2 x 256

    if (wid == 8) {
        TCGEN05_ALLOC(S_TMEMP, 512);
        TCGEN05_RELINQ();
    }
    if (tid == 0) {
        #pragma unroll
        for (int s = 0; s < NSTAGE; s++) {
            MBARRIER_INIT(MB_FULL + s * 8, 1);
            MBARRIER_INIT(MB_EMPT + s * 8, 1);
        }
        MBARRIER_INIT(MB_RES + 0, 1);
        MBARRIER_INIT(MB_RES + 8, 1);
        MBARRIER_INIT(MB_EPI + 0, 8);
        MBARRIER_INIT(MB_EPI + 8, 8);
    }
    __syncthreads();
    uint32_t tmem;
    asm volatile("ld.shared.b32 %0, [%1];" : "=r"(tmem) : "r"(S_TMEMP));

    const int nchunks = ntiles * CHUNKS_PER_TILE;

    if (tid == 256) {
        // ---------------- MMA issuer ----------------
        for (int kk = 0; kk < nchunks; kk++) {
            const int s     = kk & 3;
            const int p     = (kk >> 2) & 1;
            const int lt    = kk >> 3;
            const int chunk = kk & 7;
            const int buf   = lt & 1;
            const uint32_t st   = base + s * ST_BYTES;
            const uint32_t dbuf = tmem + buf * 256;

            MBARRIER_WAIT_PARITY(MB_FULL + s * 8, p);
            if (chunk == 0 && lt >= 2)
                MBARRIER_WAIT_PARITY(MB_EPI + buf * 8, ((lt - 2) >> 1) & 1);

            const uint64_t dAhi = make_desc64(st);
            const uint64_t dAlo = make_desc64(st + ST_ALO);
            const uint64_t dBhi = make_desc64(st + ST_BHI);
            const uint64_t dBlo = make_desc64(st + ST_BLO);
            #pragma unroll
            for (int ks = 0; ks < 2; ks++)
                mma_f16_ss(dbuf, dAhi + ks * 2, dBhi + ks * 2,
                           (chunk == 0 && ks == 0) ? 0u : 1u);
            #pragma unroll
            for (int ks = 0; ks < 2; ks++)
                mma_f16_ss(dbuf, dAhi + ks * 2, dBlo + ks * 2, 1u);
            #pragma unroll
            for (int ks = 0; ks < 2; ks++)
                mma_f16_ss(dbuf, dAlo + ks * 2, dBhi + ks * 2, 1u);

            TCGEN05_COMMIT(MB_EMPT + s * 8);
            if (chunk == CHUNKS_PER_TILE - 1) TCGEN05_COMMIT(MB_RES + buf * 8);
        }
    } else if (tid == 288) {
        // ---------------- TMA issuer ----------------
        for (int kk = 0; kk < nchunks; kk++) {
            const int s     = kk & 3;
            const int lt    = kk >> 3;
            const int chunk = kk & 7;
            const int tile  = cta + lt * NCTA;
            const int row0  = (tile >> 4) * TM;
            const int col0  = (tile & 15) * TN;
            const uint32_t st = base + s * ST_BYTES;
            const uint32_t fb = MB_FULL + s * 8;

            if (kk >= NSTAGE)
                MBARRIER_WAIT_PARITY(MB_EMPT + s * 8, ((kk - NSTAGE) >> 2) & 1);

            MBARRIER_EXPECT_TX(fb, ST_BYTES);
            tma_ld_2d(st +      0, &mVhi, chunk * 32, row0, fb);
            tma_ld_2d(st + ST_ALO, &mVlo, chunk * 32, row0, fb);
            tma_ld_2d(st + ST_BHI, &mThi, chunk * 32, col0, fb);
            tma_ld_2d(st + ST_BLO, &mTlo, chunk * 32, col0, fb);
        }
    } else if (tid < 256) {
        // ---------------- epilogue: 8 warps (0-7), branchless ----------------
        const int w   = wid;          // 0..7
        const int sub = w & 3;        // TMEM subpartition == SMSP
        const int ch2 = w >> 2;       // 128-column half
        for (int lt = 0; lt < ntiles; lt++) {
            const int buf  = lt & 1;
            const int tile = cta + lt * NCTA;
            const int row0 = (tile >> 4) * TM;
            const int col0 = (tile & 15) * TN;
            const int r    = row0 + sub * 32 + lane;
            const float dr  = g_diag[r];
            const float mdr = MARGIN - dr;
            const uint32_t dbuf = tmem + buf * 256 + ch2 * 128;
            float* mdc = s_mdc + buf * 256 + ch2 * 128;
            int cnt = 0;

            MBARRIER_WAIT_PARITY(MB_RES + buf * 8, (lt >> 1) & 1);
            TCGEN05_FENCE_AFTER();

            #pragma unroll
            for (int q = 0; q < 4; q++)
                mdc[lane + q * 32] =
                    MARGIN - g_diag[col0 + ch2 * 128 + q * 32 + lane];

            #pragma unroll 1
            for (int g = 0; g < 4; g++) {
                uint32_t dreg[32];
                TCGEN05_LD_X32(dreg, dbuf + g * 32);
                TCGEN05_WAIT_LD();
                #pragma unroll
                for (int j = 0; j < 32; j++) {
                    const int c  = col0 + ch2 * 128 + g * 32 + j;
                    const float sv = __uint_as_float(dreg[j]);
                    const float diff = sv - dr;
                    vt += fmaxf(sv + mdr, 0.f);
                    tv += fmaxf(sv + mdc[g * 32 + j], 0.f);
                    cnt += (diff > EPS) ? 1 : 0;
                    const bool tie = (fabsf(diff) <= EPS) && (c != r);
                    const unsigned m = __ballot_sync(0xFFFFFFFFu, tie);
                    if (m) {          // warp-uniform, rarely taken
                        if (tie) {
                            unsigned idx = atomicAdd(&g_ntie, 1u);
                            if (idx < MAXTIES)
                                g_tie[idx] = ((unsigned)r << 12) | (unsigned)c;
                        }
                    }
                }
            }
            TCGEN05_FENCE_BEFORE();
            if (lane == 0) MBARRIER_ARRIVE(MB_EPI + buf * 8);
            atomicAdd(&g_cnt[r], cnt);
        }
    }

    __syncthreads();
    if (wid == 8) TCGEN05_DEALLOC(tmem, 512);

#else  // ---------------- fallback: plain fp32 (not selected on GB300) -----
    for (int lt = 0; lt < ntiles; lt++) {
        const int tile = cta + lt * NCTA;
        const int row0 = (tile >> 4) * TM;
        const int col0 = (tile & 15) * TN;
        if (tid < 128) {
            const int r = row0 + tid;
            const float dr = g_diag[r];
            int cnt = 0;
            for (int cc = 0; cc < TN; cc++) {
                const int c = col0 + cc;
                float s = exact_dot(V, T, r, c);
                vt += fmaxf(0.f, MARGIN - dr + s);
                tv += fmaxf(0.f, MARGIN - g_diag[c] + s);
                if (c != r) cnt += (s > dr) ? 1 : 0;
                else { vt -= fmaxf(0.f, MARGIN - dr + s) - MARGIN;
                       tv -= fmaxf(0.f, MARGIN - dr + s) - MARGIN; }
            }
            atomicAdd(&g_cnt[r], cnt);
        }
    }
    __syncthreads();
#endif

    // loss reduction: one double atomic per warp
    #pragma unroll
    for (int off = 16; off > 0; off >>= 1) {
        vt += __shfl_down_sync(0xFFFFFFFFu, vt, off);
        tv += __shfl_down_sync(0xFFFFFFFFu, tv, off);
    }
    if (lane == 0) {
        atomicAdd(&g_vt_sum, (double)vt);
        atomicAdd(&g_tv_sum, (double)tv);
    }

    // ---- last-CTA finalize ----
    __shared__ unsigned s_last;
    __shared__ int rA[256], rB[256], rC[256], rD[256];
    __threadfence();
    __syncthreads();
    if (tid == 0) s_last = (atomicAdd(&g_done, 1u) == (unsigned)(NCTA - 1));
    __syncthreads();
    if (!s_last) return;

    // resolve near-ties exactly (few hundred expected)
    if (tid < 256) {
        unsigned nt = g_ntie;
        if (nt > MAXTIES) nt = MAXTIES;
        for (unsigned i = tid; i < nt; i += 256) {
            const unsigned pc = g_tie[i];
            const int rr = pc >> 12;
            const int cc = pc & 4095;
            const float ex = exact_dot(V, T, rr, cc);
            if (ex > g_diag[rr]) atomicAdd(&g_cnt[rr], 1);
        }
    }
    __threadfence();
    __syncthreads();

    if (tid < 256) {
        int c1 = 0, c5 = 0, c10 = 0, rs = 0;
        for (int i = tid; i < NN; i += 256) {
            int c = g_cnt[i];
            c1  += (c < 1);
            c5  += (c < 5);
            c10 += (c < 10);
            rs  += c;
        }
        rA[tid] = c1; rB[tid] = c5; rC[tid] = c10; rD[tid] = rs;
    }
    __syncthreads();
    for (int s = 128; s > 0; s >>= 1) {
        if (tid < s) {
            rA[tid] += rA[tid + s]; rB[tid] += rB[tid + s];
            rC[tid] += rC[tid + s]; rD[tid] += rD[tid + s];
        }
        __syncthreads();
    }
    if (tid == 0) {
        const double denom = (double)NN * (double)(NN - 1);
        const double diagfix = (double)NN * (double)MARGIN;  // unconditional hinge on diagonal
        out[0] = (float)((g_vt_sum - diagfix) / denom);
        out[1] = (float)((g_tv_sum - diagfix) / denom);
        out[2] = (float)rA[0] / (float)NN;
        out[3] = (float)rB[0] / (float)NN;
        out[4] = (float)rC[0] / (float)NN;
        out[5] = (float)rD[0] / (float)NN;
    }
}

// ---------------------------------------------------------------------------
typedef CUresult (*EncodeFn)(CUtensorMap*, CUtensorMapDataType, unsigned int,
                             void*, const unsigned long long*,
                             const unsigned long long*, const unsigned int*,
                             const unsigned int*, CUtensorMapInterleave,
                             CUtensorMapSwizzle, CUtensorMapL2promotion,
                             CUtensorMapFloatOOBfill);

static void encode_map(EncodeFn enc, CUtensorMap* m, void* ptr, unsigned rows) {
    unsigned long long dims[2]    = {DD, NN};
    unsigned long long strides[1] = {DD * sizeof(__nv_bfloat16)};
    unsigned int box[2]           = {32, rows};     // 32 bf16 = 64B = SW64 span
    unsigned int es[2]            = {1, 1};
    enc(m, CU_TENSOR_MAP_DATA_TYPE_BFLOAT16, 2, ptr, dims, strides, box, es,
        CU_TENSOR_MAP_INTERLEAVE_NONE, CU_TENSOR_MAP_SWIZZLE_64B,
        CU_TENSOR_MAP_L2_PROMOTION_L2_128B, CU_TENSOR_MAP_FLOAT_OOB_FILL_NONE);
}

extern "C" void kernel_launch(void* const* d_in, const int* in_sizes, int n_in,
                              void* d_out, int out_size) {
    (void)in_sizes; (void)n_in; (void)out_size;
    const float* V = (const float*)d_in[0];
    const float* T = (const float*)d_in[1];
    float* out = (float*)d_out;

    void *pVhi, *pVlo, *pThi, *pTlo;
    cudaGetSymbolAddress(&pVhi, g_Vhi);
    cudaGetSymbolAddress(&pVlo, g_Vlo);
    cudaGetSymbolAddress(&pThi, g_Thi);
    cudaGetSymbolAddress(&pTlo, g_Tlo);

    void* sym = nullptr;
    cudaDriverEntryPointQueryResult qr;
    cudaGetDriverEntryPointByVersion("cuTensorMapEncodeTiled", &sym, 12000,
                                     cudaEnableDefault, &qr);
    EncodeFn enc = (EncodeFn)sym;

    CUtensorMap mVhi, mVlo, mThi, mTlo;
    encode_map(enc, &mVhi, pVhi, TM);   // A tiles: 128 rows
    encode_map(enc, &mVlo, pVlo, TM);
    encode_map(enc, &mThi, pThi, TN);   // B tiles: 256 rows
    encode_map(enc, &mTlo, pTlo, TN);

    cudaFuncSetAttribute(gemm_tc_kernel,
                         cudaFuncAttributeMaxDynamicSharedMemorySize, SMEM_DYN);

    init_kernel<<<NN * 32 / 256, 256>>>(V, T);
    gemm_tc_kernel<<<NCTA, NTHREADS, SMEM_DYN>>>(
        mVhi, mVlo, mThi, mTlo, V, T, out);
}

// round 12
// speedup vs baseline: 1.0382x; 1.0382x over previous
#include <cuda_runtime.h>
#include <cuda_bf16.h>
#include <cuda.h>
#include <stdint.h>

#define NN 4096
#define DD 256
#define MARGIN 0.1f
#define EPS 0.002f
#define MAXTIES 65536

#if defined(__CUDA_ARCH_FEAT_SM103_ALL) || defined(__CUDA_ARCH_FEAT_SM100_ALL)
#define HAS_TCGEN05 1
#else
#define HAS_TCGEN05 0
#endif

// idesc kind::f16: dtype=F32, atype=btype=BF16, N=256, M=128 (cg1)
#define IDESC 0x08400490u

// tile geometry
#define TM 128
#define TN 256
#define TILES_X (NN / TN)            // 16
#define TILES_Y (NN / TM)            // 32
#define NTILES  (TILES_X * TILES_Y)  // 512
#define NCTA    148
#define NTHREADS 320                 // 8 epilogue warps + MMA warp + TMA warp

// chunk = K=32 (64B rows, SW64). stage: Ahi 8K | Alo 8K | Bhi 16K | Blo 16K
#define ST_ALO   8192
#define ST_BHI   16384
#define ST_BLO   32768
#define ST_BYTES 49152
#define NSTAGE   4
#define CHUNKS_PER_TILE 8            // 256 / 32

#define OFF_TMEMP  (NSTAGE * ST_BYTES)       // 196608
#define OFF_MB     (OFF_TMEMP + 16)
#define MB_FULL_O  0                          // 4 x 8B
#define MB_EMPT_O  32                         // 4 x 8B
#define MB_RES_O   64                         // 2 x 8B
#define MB_EPI_O   80                         // 2 x 8B
#define OFF_DC     (OFF_TMEMP + 128)          // 2 x 256 floats
#define SMEM_DYN   (OFF_DC + 2048 + 1024)

typedef unsigned long long u64;

// ---- device-global scratch ----
__device__ double g_vt_sum;
__device__ double g_tv_sum;
__device__ unsigned g_done;
__device__ unsigned g_ntie;
__device__ unsigned g_tie[MAXTIES];
__device__ int    g_cnt[NN];
__device__ float  g_diag[NN];
__device__ __align__(1024) __nv_bfloat16 g_Vhi[NN * DD];
__device__ __align__(1024) __nv_bfloat16 g_Vlo[NN * DD];
__device__ __align__(1024) __nv_bfloat16 g_Thi[NN * DD];
__device__ __align__(1024) __nv_bfloat16 g_Tlo[NN * DD];

// ======================= PTX helpers =======================
__device__ __forceinline__ uint32_t smem_u32(const void* p) {
    uint32_t a;
    asm("{ .reg .u64 t; cvta.to.shared.u64 t, %1; cvt.u32.u64 %0, t; }"
        : "=r"(a) : "l"(p));
    return a;
}

#define MBARRIER_INIT(addr, cnt) \
    asm volatile("mbarrier.init.shared.b64 [%0], %1;" \
        :: "r"((uint32_t)(addr)), "r"((uint32_t)(cnt)) : "memory")

#define MBARRIER_EXPECT_TX(addr, bytes) \
    asm volatile("mbarrier.arrive.expect_tx.shared.b64 _, [%0], %1;" \
        :: "r"((uint32_t)(addr)), "r"((uint32_t)(bytes)) : "memory")

#define MBARRIER_ARRIVE(addr) \
    asm volatile("mbarrier.arrive.shared.b64 _, [%0];" \
        :: "r"((uint32_t)(addr)) : "memory")

#define MBARRIER_WAIT_PARITY(addr, parity) do {                                   \
    uint32_t _mb = (uint32_t)(addr);                                              \
    uint32_t _ph = (uint32_t)(parity);                                            \
    uint32_t _done;                                                               \
    asm volatile("{\n\t.reg .pred p;\n\t"                                         \
        "mbarrier.try_wait.parity.acquire.cta.shared::cta.b64 p, [%1], %2;\n\t"   \
        "selp.b32 %0, 1, 0, p;\n\t}"                                              \
        : "=r"(_done) : "r"(_mb), "r"(_ph) : "memory");                           \
    if (!_done) {                                                                 \
        asm volatile("{\n\t.reg .pred P1;\n\t"                                    \
            "W_%=:\n\t"                                                           \
            "mbarrier.try_wait.parity.acquire.cta.shared::cta.b64 P1, [%0], %1, 0x989680;\n\t" \
            "@P1 bra.uni D_%=;\n\t"                                               \
            "bra.uni W_%=;\n\t"                                                   \
            "D_%=:\n\t}"                                                          \
            :: "r"(_mb), "r"(_ph) : "memory");                                    \
    }                                                                             \
} while (0)

#if HAS_TCGEN05
#define TCGEN05_ALLOC(res_addr, ncols) \
    asm volatile("tcgen05.alloc.cta_group::1.sync.aligned.shared::cta.b32 [%0], %1;" \
        :: "r"((uint32_t)(res_addr)), "r"((uint32_t)(ncols)) : "memory")
#define TCGEN05_RELINQ() \
    asm volatile("tcgen05.relinquish_alloc_permit.cta_group::1.sync.aligned;")
#define TCGEN05_DEALLOC(tmem, ncols) \
    asm volatile("tcgen05.dealloc.cta_group::1.sync.aligned.b32 %0, %1;" \
        :: "r"(tmem), "r"((uint32_t)(ncols)))
#define TCGEN05_COMMIT(mbar) \
    asm volatile("tcgen05.commit.cta_group::1.mbarrier::arrive::one.shared::cluster.b64 [%0];" \
        :: "r"((uint32_t)(mbar)) : "memory")
#define TCGEN05_FENCE_AFTER() \
    asm volatile("tcgen05.fence::after_thread_sync;" ::: "memory")
#define TCGEN05_FENCE_BEFORE() \
    asm volatile("tcgen05.fence::before_thread_sync;" ::: "memory")
#define TCGEN05_WAIT_LD() \
    asm volatile("tcgen05.wait::ld.sync.aligned;" ::: "memory")

#define TCGEN05_LD_X32(r, addr) \
    asm volatile("tcgen05.ld.sync.aligned.32x32b.x32.b32 " \
        "{%0, %1, %2, %3, %4, %5, %6, %7, %8, %9, %10, %11, %12, %13, %14, %15, " \
        " %16, %17, %18, %19, %20, %21, %22, %23, %24, %25, %26, %27, %28, %29, %30, %31}, [%32];" \
        : "=r"((r)[0]),  "=r"((r)[1]),  "=r"((r)[2]),  "=r"((r)[3]),  \
          "=r"((r)[4]),  "=r"((r)[5]),  "=r"((r)[6]),  "=r"((r)[7]),  \
          "=r"((r)[8]),  "=r"((r)[9]),  "=r"((r)[10]), "=r"((r)[11]), \
          "=r"((r)[12]), "=r"((r)[13]), "=r"((r)[14]), "=r"((r)[15]), \
          "=r"((r)[16]), "=r"((r)[17]), "=r"((r)[18]), "=r"((r)[19]), \
          "=r"((r)[20]), "=r"((r)[21]), "=r"((r)[22]), "=r"((r)[23]), \
          "=r"((r)[24]), "=r"((r)[25]), "=r"((r)[26]), "=r"((r)[27]), \
          "=r"((r)[28]), "=r"((r)[29]), "=r"((r)[30]), "=r"((r)[31]) \
        : "r"(addr))

// SW64 SMEM descriptor: layout=SW64(4), version=1, SBO=32, LBO=1
static __device__ __forceinline__ uint64_t make_desc64(uint32_t addr) {
    const uint64_t BASE =
        (uint64_t(4)  << 61) | (uint64_t(1) << 46) |
        (uint64_t(32) << 32) | (uint64_t(1) << 16);
    return BASE | ((uint64_t)(addr >> 4) & 0x3FFF);
}

__device__ __forceinline__ void tma_ld_2d(uint32_t dst, const void* map,
                                          int cx, int cy, uint32_t mbar) {
    asm volatile(
        "cp.async.bulk.tensor.2d.shared::cta.global.tile.mbarrier::complete_tx::bytes "
        "[%0], [%1, {%2, %3}], [%4];"
        :: "r"(dst), "l"(map), "r"(cx), "r"(cy), "r"(mbar) : "memory");
}

__device__ __forceinline__ void mma_f16_ss(uint32_t d, uint64_t da, uint64_t db,
                                           uint32_t en) {
    asm volatile("{\n\t.reg .pred p;\n\tsetp.ne.u32 p, %4, 0;\n\t"
        "tcgen05.mma.cta_group::1.kind::f16 [%0], %1, %2, %3, {%5, %5, %5, %5}, p;\n\t}"
        :: "r"(d), "l"(da), "l"(db), "r"(IDESC), "r"(en), "r"(0u) : "memory");
}
#endif  // HAS_TCGEN05

// ---------------------------------------------------------------------------
__device__ __forceinline__ void split4(float4 a, uint2& h, uint2& l) {
    __nv_bfloat162 hxy = __floats2bfloat162_rn(a.x, a.y);
    __nv_bfloat162 hzw = __floats2bfloat162_rn(a.z, a.w);
    float2 fxy = __bfloat1622float2(hxy);
    float2 fzw = __bfloat1622float2(hzw);
    __nv_bfloat162 lxy = __floats2bfloat162_rn(a.x - fxy.x, a.y - fxy.y);
    __nv_bfloat162 lzw = __floats2bfloat162_rn(a.z - fzw.x, a.w - fzw.y);
    h.x = reinterpret_cast<unsigned&>(hxy);
    h.y = reinterpret_cast<unsigned&>(hzw);
    l.x = reinterpret_cast<unsigned&>(lxy);
    l.y = reinterpret_cast<unsigned&>(lzw);
}

// exact fp32 dot of row r of V with row c of T (2-way ILP)
__device__ __forceinline__ float exact_dot(const float* __restrict__ V,
                                           const float* __restrict__ T,
                                           int r, int c) {
    const float4* a4 = reinterpret_cast<const float4*>(V + (size_t)r * DD);
    const float4* b4 = reinterpret_cast<const float4*>(T + (size_t)c * DD);
    float e0 = 0.f, e1 = 0.f;
    #pragma unroll 8
    for (int k = 0; k < DD / 4; k += 2) {
        float4 x = a4[k],      y = b4[k];
        float4 x1 = a4[k + 1], y1 = b4[k + 1];
        e0 += x.x * y.x + x.y * y.y + x.z * y.z + x.w * y.w;
        e1 += x1.x * y1.x + x1.y * y1.y + x1.z * y1.z + x1.w * y1.w;
    }
    return e0 + e1;
}

// ---------------------------------------------------------------------------
// Kernel 1: fused init — bf16 hi/lo split, exact fp32 diag, zero counters.
// ---------------------------------------------------------------------------
__global__ void init_kernel(const float* __restrict__ V,
                            const float* __restrict__ T) {
    const int gtid = blockIdx.x * blockDim.x + threadIdx.x;
    const int row  = gtid >> 5;
    const int lane = gtid & 31;
    if (gtid == 0) { g_vt_sum = 0.0; g_tv_sum = 0.0; g_done = 0u; g_ntie = 0u; }
    if (row >= NN) return;

    const float4* v4 = reinterpret_cast<const float4*>(V + (size_t)row * DD);
    const float4* t4 = reinterpret_cast<const float4*>(T + (size_t)row * DD);
    uint2* vh = reinterpret_cast<uint2*>(g_Vhi + (size_t)row * DD);
    uint2* vl = reinterpret_cast<uint2*>(g_Vlo + (size_t)row * DD);
    uint2* th = reinterpret_cast<uint2*>(g_Thi + (size_t)row * DD);
    uint2* tl = reinterpret_cast<uint2*>(g_Tlo + (size_t)row * DD);

    float acc = 0.f;
    #pragma unroll
    for (int p = 0; p < 2; p++) {
        const int idx = lane + p * 32;
        float4 a = v4[idx];
        float4 b = t4[idx];
        acc += a.x * b.x + a.y * b.y + a.z * b.z + a.w * b.w;
        uint2 h, l;
        split4(a, h, l); vh[idx] = h; vl[idx] = l;
        split4(b, h, l); th[idx] = h; tl[idx] = l;
    }
    #pragma unroll
    for (int off = 16; off > 0; off >>= 1)
        acc += __shfl_down_sync(0xFFFFFFFFu, acc, off);
    if (lane == 0) { g_diag[row] = acc; g_cnt[row] = 0; }
}

// ---------------------------------------------------------------------------
// Kernel 2: persistent warp-specialized tcgen05 GEMM, 4-stage TMA pipeline
// (K=32 chunks, SW64), decoupled MMA/TMA issuers, BRANCHLESS epilogue with
// per-group tie bitmask (no ballots, no per-element branches).
// 148 CTAs x 320 threads:
//   warps 0-7 : epilogue — warp w: rows (w&3)*32+lane, cols [(w>>2)*128,+128)
//   warp  8   : lane 0 = MMA issuer (also TMEM alloc)
//   warp  9   : lane 0 = TMA issuer
// ---------------------------------------------------------------------------
__global__ __launch_bounds__(NTHREADS, 1)
void gemm_tc_kernel(const __grid_constant__ CUtensorMap mVhi,
                    const __grid_constant__ CUtensorMap mVlo,
                    const __grid_constant__ CUtensorMap mThi,
                    const __grid_constant__ CUtensorMap mTlo,
                    const float* __restrict__ V,
                    const float* __restrict__ T,
                    float* __restrict__ out) {
    extern __shared__ char smem_raw[];
    const uint32_t raw  = smem_u32(smem_raw);
    const uint32_t base = (raw + 1023) & ~1023u;
    char* gbase = smem_raw + (base - raw);

    const int tid  = threadIdx.x;
    const int lane = tid & 31;
    const int cta  = blockIdx.x;
    const int ntiles = (NTILES - cta + NCTA - 1) / NCTA;

    float vt = 0.f, tv = 0.f;

#if HAS_TCGEN05
    const int wid = tid >> 5;
    const uint32_t S_TMEMP = base + OFF_TMEMP;
    const uint32_t MB_FULL = base + OFF_MB + MB_FULL_O;  // 4 stages
    const uint32_t MB_EMPT = base + OFF_MB + MB_EMPT_O;  // 4 stages
    const uint32_t MB_RES  = base + OFF_MB + MB_RES_O;   // 2 bufs
    const uint32_t MB_EPI  = base + OFF_MB + MB_EPI_O;   // 2 bufs
    float* s_mdc = reinterpret_cast<float*>(gbase + OFF_DC);  // 2 x 256

    if (wid == 8) {
        TCGEN05_ALLOC(S_TMEMP, 512);
        TCGEN05_RELINQ();
    }
    if (tid == 0) {
        #pragma unroll
        for (int s = 0; s < NSTAGE; s++) {
            MBARRIER_INIT(MB_FULL + s * 8, 1);
            MBARRIER_INIT(MB_EMPT + s * 8, 1);
        }
        MBARRIER_INIT(MB_RES + 0, 1);
        MBARRIER_INIT(MB_RES + 8, 1);
        MBARRIER_INIT(MB_EPI + 0, 8);
        MBARRIER_INIT(MB_EPI + 8, 8);
    }
    __syncthreads();
    uint32_t tmem;
    asm volatile("ld.shared.b32 %0, [%1];" : "=r"(tmem) : "r"(S_TMEMP));

    const int nchunks = ntiles * CHUNKS_PER_TILE;

    if (tid == 256) {
        // ---------------- MMA issuer ----------------
        for (int kk = 0; kk < nchunks; kk++) {
            const int s     = kk & 3;
            const int p     = (kk >> 2) & 1;
            const int lt    = kk >> 3;
            const int chunk = kk & 7;
            const int buf   = lt & 1;
            const uint32_t st   = base + s * ST_BYTES;
            const uint32_t dbuf = tmem + buf * 256;

            MBARRIER_WAIT_PARITY(MB_FULL + s * 8, p);
            if (chunk == 0 && lt >= 2)
                MBARRIER_WAIT_PARITY(MB_EPI + buf * 8, ((lt - 2) >> 1) & 1);

            const uint64_t dAhi = make_desc64(st);
            const uint64_t dAlo = make_desc64(st + ST_ALO);
            const uint64_t dBhi = make_desc64(st + ST_BHI);
            const uint64_t dBlo = make_desc64(st + ST_BLO);
            #pragma unroll
            for (int ks = 0; ks < 2; ks++)
                mma_f16_ss(dbuf, dAhi + ks * 2, dBhi + ks * 2,
                           (chunk == 0 && ks == 0) ? 0u : 1u);
            #pragma unroll
            for (int ks = 0; ks < 2; ks++)
                mma_f16_ss(dbuf, dAhi + ks * 2, dBlo + ks * 2, 1u);
            #pragma unroll
            for (int ks = 0; ks < 2; ks++)
                mma_f16_ss(dbuf, dAlo + ks * 2, dBhi + ks * 2, 1u);

            TCGEN05_COMMIT(MB_EMPT + s * 8);
            if (chunk == CHUNKS_PER_TILE - 1) TCGEN05_COMMIT(MB_RES + buf * 8);
        }
    } else if (tid == 288) {
        // ---------------- TMA issuer ----------------
        for (int kk = 0; kk < nchunks; kk++) {
            const int s     = kk & 3;
            const int lt    = kk >> 3;
            const int chunk = kk & 7;
            const int tile  = cta + lt * NCTA;
            const int row0  = (tile >> 4) * TM;
            const int col0  = (tile & 15) * TN;
            const uint32_t st = base + s * ST_BYTES;
            const uint32_t fb = MB_FULL + s * 8;

            if (kk >= NSTAGE)
                MBARRIER_WAIT_PARITY(MB_EMPT + s * 8, ((kk - NSTAGE) >> 2) & 1);

            MBARRIER_EXPECT_TX(fb, ST_BYTES);
            tma_ld_2d(st +      0, &mVhi, chunk * 32, row0, fb);
            tma_ld_2d(st + ST_ALO, &mVlo, chunk * 32, row0, fb);
            tma_ld_2d(st + ST_BHI, &mThi, chunk * 32, col0, fb);
            tma_ld_2d(st + ST_BLO, &mTlo, chunk * 32, col0, fb);
        }
    } else if (tid < 256) {
        // ---------- epilogue: 8 warps, branchless + per-group tie bitmask ----
        const int w   = wid;          // 0..7
        const int sub = w & 3;        // TMEM subpartition == SMSP
        const int ch2 = w >> 2;       // 128-column half
        for (int lt = 0; lt < ntiles; lt++) {
            const int buf  = lt & 1;
            const int tile = cta + lt * NCTA;
            const int row0 = (tile >> 4) * TM;
            const int col0 = (tile & 15) * TN;
            const int r    = row0 + sub * 32 + lane;
            const float dr  = g_diag[r];
            const float mdr = MARGIN - dr;
            const uint32_t dbuf = tmem + buf * 256 + ch2 * 128;
            float* mdc = s_mdc + buf * 256 + ch2 * 128;
            int cnt = 0;

            MBARRIER_WAIT_PARITY(MB_RES + buf * 8, (lt >> 1) & 1);
            TCGEN05_FENCE_AFTER();

            #pragma unroll
            for (int q = 0; q < 4; q++)
                mdc[lane + q * 32] =
                    MARGIN - g_diag[col0 + ch2 * 128 + q * 32 + lane];

            #pragma unroll 1
            for (int g = 0; g < 4; g++) {
                uint32_t dreg[32];
                TCGEN05_LD_X32(dreg, dbuf + g * 32);
                TCGEN05_WAIT_LD();
                uint32_t tiebits = 0u;
                #pragma unroll
                for (int j = 0; j < 32; j++) {
                    const float sv = __uint_as_float(dreg[j]);
                    const float diff = sv - dr;
                    vt += fmaxf(sv + mdr, 0.f);
                    tv += fmaxf(sv + mdc[g * 32 + j], 0.f);
                    cnt += (diff > EPS) ? 1 : 0;
                    tiebits |= (fabsf(diff) <= EPS) ? (1u << j) : 0u;
                }
                if (tiebits) {   // rare (diagonal thread + true near-ties)
                    do {
                        const int j = __ffs(tiebits) - 1;
                        tiebits &= tiebits - 1u;
                        const int c = col0 + ch2 * 128 + g * 32 + j;
                        if (c != r) {
                            unsigned idx = atomicAdd(&g_ntie, 1u);
                            if (idx < MAXTIES)
                                g_tie[idx] = ((unsigned)r << 12) | (unsigned)c;
                        }
                    } while (tiebits);
                }
            }
            TCGEN05_FENCE_BEFORE();
            if (lane == 0) MBARRIER_ARRIVE(MB_EPI + buf * 8);
            atomicAdd(&g_cnt[r], cnt);
        }
    }

    __syncthreads();
    if (wid == 8) TCGEN05_DEALLOC(tmem, 512);

#else  // ---------------- fallback: plain fp32 (not selected on GB300) -----
    for (int lt = 0; lt < ntiles; lt++) {
        const int tile = cta + lt * NCTA;
        const int row0 = (tile >> 4) * TM;
        const int col0 = (tile & 15) * TN;
        if (tid < 128) {
            const int r = row0 + tid;
            const float dr = g_diag[r];
            int cnt = 0;
            for (int cc = 0; cc < TN; cc++) {
                const int c = col0 + cc;
                float s = exact_dot(V, T, r, c);
                vt += fmaxf(0.f, MARGIN - dr + s);
                tv += fmaxf(0.f, MARGIN - g_diag[c] + s);
                if (c != r) cnt += (s > dr) ? 1 : 0;
                else { vt -= fmaxf(0.f, MARGIN - dr + s) - MARGIN;
                       tv -= fmaxf(0.f, MARGIN - dr + s) - MARGIN; }
            }
            atomicAdd(&g_cnt[r], cnt);
        }
    }
    __syncthreads();
#endif

    // loss reduction: one double atomic per warp
    #pragma unroll
    for (int off = 16; off > 0; off >>= 1) {
        vt += __shfl_down_sync(0xFFFFFFFFu, vt, off);
        tv += __shfl_down_sync(0xFFFFFFFFu, tv, off);
    }
    if (lane == 0) {
        atomicAdd(&g_vt_sum, (double)vt);
        atomicAdd(&g_tv_sum, (double)tv);
    }

    // ---- last-CTA finalize ----
    __shared__ unsigned s_last;
    __shared__ int rA[256], rB[256], rC[256], rD[256];
    __threadfence();
    __syncthreads();
    if (tid == 0) s_last = (atomicAdd(&g_done, 1u) == (unsigned)(NCTA - 1));
    __syncthreads();
    if (!s_last) return;

    // resolve near-ties exactly (few thousand worst case)
    if (tid < 256) {
        unsigned nt = g_ntie;
        if (nt > MAXTIES) nt = MAXTIES;
        for (unsigned i = tid; i < nt; i += 256) {
            const unsigned pc = g_tie[i];
            const int rr = pc >> 12;
            const int cc = pc & 4095;
            const float ex = exact_dot(V, T, rr, cc);
            if (ex > g_diag[rr]) atomicAdd(&g_cnt[rr], 1);
        }
    }
    __threadfence();
    __syncthreads();

    if (tid < 256) {
        int c1 = 0, c5 = 0, c10 = 0, rs = 0;
        for (int i = tid; i < NN; i += 256) {
            int c = g_cnt[i];
            c1  += (c < 1);
            c5  += (c < 5);
            c10 += (c < 10);
            rs  += c;
        }
        rA[tid] = c1; rB[tid] = c5; rC[tid] = c10; rD[tid] = rs;
    }
    __syncthreads();
    for (int s = 128; s > 0; s >>= 1) {
        if (tid < s) {
            rA[tid] += rA[tid + s]; rB[tid] += rB[tid + s];
            rC[tid] += rC[tid + s]; rD[tid] += rD[tid + s];
        }
        __syncthreads();
    }
    if (tid == 0) {
        const double denom = (double)NN * (double)(NN - 1);
        const double diagfix = (double)NN * (double)MARGIN;  // diagonal hinge
        out[0] = (float)((g_vt_sum - diagfix) / denom);
        out[1] = (float)((g_tv_sum - diagfix) / denom);
        out[2] = (float)rA[0] / (float)NN;
        out[3] = (float)rB[0] / (float)NN;
        out[4] = (float)rC[0] / (float)NN;
        out[5] = (float)rD[0] / (float)NN;
    }
}

// ---------------------------------------------------------------------------
typedef CUresult (*EncodeFn)(CUtensorMap*, CUtensorMapDataType, unsigned int,
                             void*, const unsigned long long*,
                             const unsigned long long*, const unsigned int*,
                             const unsigned int*, CUtensorMapInterleave,
                             CUtensorMapSwizzle, CUtensorMapL2promotion,
                             CUtensorMapFloatOOBfill);

static void encode_map(EncodeFn enc, CUtensorMap* m, void* ptr, unsigned rows) {
    unsigned long long dims[2]    = {DD, NN};
    unsigned long long strides[1] = {DD * sizeof(__nv_bfloat16)};
    unsigned int box[2]           = {32, rows};     // 32 bf16 = 64B = SW64 span
    unsigned int es[2]            = {1, 1};
    enc(m, CU_TENSOR_MAP_DATA_TYPE_BFLOAT16, 2, ptr, dims, strides, box, es,
        CU_TENSOR_MAP_INTERLEAVE_NONE, CU_TENSOR_MAP_SWIZZLE_64B,
        CU_TENSOR_MAP_L2_PROMOTION_L2_128B, CU_TENSOR_MAP_FLOAT_OOB_FILL_NONE);
}

extern "C" void kernel_launch(void* const* d_in, const int* in_sizes, int n_in,
                              void* d_out, int out_size) {
    (void)in_sizes; (void)n_in; (void)out_size;
    const float* V = (const float*)d_in[0];
    const float* T = (const float*)d_in[1];
    float* out = (float*)d_out;

    void *pVhi, *pVlo, *pThi, *pTlo;
    cudaGetSymbolAddress(&pVhi, g_Vhi);
    cudaGetSymbolAddress(&pVlo, g_Vlo);
    cudaGetSymbolAddress(&pThi, g_Thi);
    cudaGetSymbolAddress(&pTlo, g_Tlo);

    void* sym = nullptr;
    cudaDriverEntryPointQueryResult qr;
    cudaGetDriverEntryPointByVersion("cuTensorMapEncodeTiled", &sym, 12000,
                                     cudaEnableDefault, &qr);
    EncodeFn enc = (EncodeFn)sym;

    CUtensorMap mVhi, mVlo, mThi, mTlo;
    encode_map(enc, &mVhi, pVhi, TM);   // A tiles: 128 rows
    encode_map(enc, &mVlo, pVlo, TM);
    encode_map(enc, &mThi, pThi, TN);   // B tiles: 256 rows
    encode_map(enc, &mTlo, pTlo, TN);

    cudaFuncSetAttribute(gemm_tc_kernel,
                         cudaFuncAttributeMaxDynamicSharedMemorySize, SMEM_DYN);

    init_kernel<<<NN * 32 / 256, 256>>>(V, T);
    gemm_tc_kernel<<<NCTA, NTHREADS, SMEM_DYN>>>(
        mVhi, mVlo, mThi, mTlo, V, T, out);
}

// round 13
// speedup vs baseline: 3.1008x; 2.9868x over previous
#include <cuda_runtime.h>
#include <cuda_bf16.h>
#include <cuda.h>
#include <stdint.h>

#define NN 4096
#define DD 256
#define MARGIN 0.1f
#define EPS 0.002f

#if defined(__CUDA_ARCH_FEAT_SM103_ALL) || defined(__CUDA_ARCH_FEAT_SM100_ALL)
#define HAS_TCGEN05 1
#else
#define HAS_TCGEN05 0
#endif

// idesc kind::f16: dtype=F32, atype=btype=BF16, N=256, M=128 (cg1)
#define IDESC 0x08400490u

// tile geometry
#define TM 128
#define TN 256
#define TILES_X (NN / TN)            // 16
#define TILES_Y (NN / TM)            // 32
#define NTILES  (TILES_X * TILES_Y)  // 512
#define NCTA    148
#define NTHREADS 544                 // 16 consumer warps + 1 producer warp

// stage layout (bytes): Ahi 16K | Alo 16K | Bhi 32K | Blo 32K
#define ST_ALO   16384
#define ST_BHI   32768
#define ST_BLO   65536
#define ST_BYTES 98304
#define OFF_TMEMP  (2 * ST_BYTES)         // 196608
#define OFF_MB     (OFF_TMEMP + 16)       // 8 mbarriers
#define OFF_DC     (OFF_TMEMP + 128)      // 2 x 256 floats
#define SMEM_DYN   (OFF_DC + 2048 + 1024)

typedef unsigned long long u64;

// ---- device-global scratch ----
__device__ double g_vt_sum;
__device__ double g_tv_sum;
__device__ unsigned g_done;
__device__ int    g_cnt[NN];
__device__ float  g_diag[NN];
__device__ __align__(1024) __nv_bfloat16 g_Vhi[NN * DD];
__device__ __align__(1024) __nv_bfloat16 g_Vlo[NN * DD];
__device__ __align__(1024) __nv_bfloat16 g_Thi[NN * DD];
__device__ __align__(1024) __nv_bfloat16 g_Tlo[NN * DD];

// ======================= PTX helpers =======================
__device__ __forceinline__ uint32_t smem_u32(const void* p) {
    uint32_t a;
    asm("{ .reg .u64 t; cvta.to.shared.u64 t, %1; cvt.u32.u64 %0, t; }"
        : "=r"(a) : "l"(p));
    return a;
}

#define MBARRIER_INIT(addr, cnt) \
    asm volatile("mbarrier.init.shared.b64 [%0], %1;" \
        :: "r"((uint32_t)(addr)), "r"((uint32_t)(cnt)) : "memory")

#define MBARRIER_EXPECT_TX(addr, bytes) \
    asm volatile("mbarrier.arrive.expect_tx.shared.b64 _, [%0], %1;" \
        :: "r"((uint32_t)(addr)), "r"((uint32_t)(bytes)) : "memory")

#define MBARRIER_ARRIVE(addr) \
    asm volatile("mbarrier.arrive.shared.b64 _, [%0];" \
        :: "r"((uint32_t)(addr)) : "memory")

#define MBARRIER_WAIT_PARITY(addr, parity) do {                                   \
    uint32_t _mb = (uint32_t)(addr);                                              \
    uint32_t _ph = (uint32_t)(parity);                                            \
    uint32_t _done;                                                               \
    asm volatile("{\n\t.reg .pred p;\n\t"                                         \
        "mbarrier.try_wait.parity.acquire.cta.shared::cta.b64 p, [%1], %2;\n\t"   \
        "selp.b32 %0, 1, 0, p;\n\t}"                                              \
        : "=r"(_done) : "r"(_mb), "r"(_ph) : "memory");                           \
    if (!_done) {                                                                 \
        asm volatile("{\n\t.reg .pred P1;\n\t"                                    \
            "W_%=:\n\t"                                                           \
            "mbarrier.try_wait.parity.acquire.cta.shared::cta.b64 P1, [%0], %1, 0x989680;\n\t" \
            "@P1 bra.uni D_%=;\n\t"                                               \
            "bra.uni W_%=;\n\t"                                                   \
            "D_%=:\n\t}"                                                          \
            :: "r"(_mb), "r"(_ph) : "memory");                                    \
    }                                                                             \
} while (0)

#if HAS_TCGEN05
#define TCGEN05_ALLOC(res_addr, ncols) \
    asm volatile("tcgen05.alloc.cta_group::1.sync.aligned.shared::cta.b32 [%0], %1;" \
        :: "r"((uint32_t)(res_addr)), "r"((uint32_t)(ncols)) : "memory")
#define TCGEN05_RELINQ() \
    asm volatile("tcgen05.relinquish_alloc_permit.cta_group::1.sync.aligned;")
#define TCGEN05_DEALLOC(tmem, ncols) \
    asm volatile("tcgen05.dealloc.cta_group::1.sync.aligned.b32 %0, %1;" \
        :: "r"(tmem), "r"((uint32_t)(ncols)))
#define TCGEN05_COMMIT(mbar) \
    asm volatile("tcgen05.commit.cta_group::1.mbarrier::arrive::one.shared::cluster.b64 [%0];" \
        :: "r"((uint32_t)(mbar)) : "memory")
#define TCGEN05_FENCE_AFTER() \
    asm volatile("tcgen05.fence::after_thread_sync;" ::: "memory")
#define TCGEN05_FENCE_BEFORE() \
    asm volatile("tcgen05.fence::before_thread_sync;" ::: "memory")
#define TCGEN05_WAIT_LD() \
    asm volatile("tcgen05.wait::ld.sync.aligned;" ::: "memory")

#define TCGEN05_LD_X32(r, addr) \
    asm volatile("tcgen05.ld.sync.aligned.32x32b.x32.b32 " \
        "{%0, %1, %2, %3, %4, %5, %6, %7, %8, %9, %10, %11, %12, %13, %14, %15, " \
        " %16, %17, %18, %19, %20, %21, %22, %23, %24, %25, %26, %27, %28, %29, %30, %31}, [%32];" \
        : "=r"((r)[0]),  "=r"((r)[1]),  "=r"((r)[2]),  "=r"((r)[3]),  \
          "=r"((r)[4]),  "=r"((r)[5]),  "=r"((r)[6]),  "=r"((r)[7]),  \
          "=r"((r)[8]),  "=r"((r)[9]),  "=r"((r)[10]), "=r"((r)[11]), \
          "=r"((r)[12]), "=r"((r)[13]), "=r"((r)[14]), "=r"((r)[15]), \
          "=r"((r)[16]), "=r"((r)[17]), "=r"((r)[18]), "=r"((r)[19]), \
          "=r"((r)[20]), "=r"((r)[21]), "=r"((r)[22]), "=r"((r)[23]), \
          "=r"((r)[24]), "=r"((r)[25]), "=r"((r)[26]), "=r"((r)[27]), \
          "=r"((r)[28]), "=r"((r)[29]), "=r"((r)[30]), "=r"((r)[31]) \
        : "r"(addr))

// SW128 SMEM descriptor: layout=SW128(2), version=1, SBO=64, LBO=1
static __device__ __forceinline__ uint64_t make_desc(uint32_t addr) {
    const uint64_t BASE =
        (uint64_t(2)  << 61) | (uint64_t(1) << 46) |
        (uint64_t(64) << 32) | (uint64_t(1) << 16);
    return BASE | ((uint64_t)(addr >> 4) & 0x3FFF);
}

__device__ __forceinline__ void tma_ld_2d(uint32_t dst, const void* map,
                                          int cx, int cy, uint32_t mbar) {
    asm volatile(
        "cp.async.bulk.tensor.2d.shared::cta.global.tile.mbarrier::complete_tx::bytes "
        "[%0], [%1, {%2, %3}], [%4];"
        :: "r"(dst), "l"(map), "r"(cx), "r"(cy), "r"(mbar) : "memory");
}

__device__ __forceinline__ void mma_f16_ss(uint32_t d, uint64_t da, uint64_t db,
                                           uint32_t en) {
    asm volatile("{\n\t.reg .pred p;\n\tsetp.ne.u32 p, %4, 0;\n\t"
        "tcgen05.mma.cta_group::1.kind::f16 [%0], %1, %2, %3, {%5, %5, %5, %5}, p;\n\t}"
        :: "r"(d), "l"(da), "l"(db), "r"(IDESC), "r"(en), "r"(0u) : "memory");
}
#endif  // HAS_TCGEN05

// ---------------------------------------------------------------------------
__device__ __forceinline__ void split4(float4 a, uint2& h, uint2& l) {
    __nv_bfloat162 hxy = __floats2bfloat162_rn(a.x, a.y);
    __nv_bfloat162 hzw = __floats2bfloat162_rn(a.z, a.w);
    float2 fxy = __bfloat1622float2(hxy);
    float2 fzw = __bfloat1622float2(hzw);
    __nv_bfloat162 lxy = __floats2bfloat162_rn(a.x - fxy.x, a.y - fxy.y);
    __nv_bfloat162 lzw = __floats2bfloat162_rn(a.z - fzw.x, a.w - fzw.y);
    h.x = reinterpret_cast<unsigned&>(hxy);
    h.y = reinterpret_cast<unsigned&>(hzw);
    l.x = reinterpret_cast<unsigned&>(lxy);
    l.y = reinterpret_cast<unsigned&>(lzw);
}

// ---------------------------------------------------------------------------
// Kernel 1: fused init — bf16 hi/lo split, exact fp32 diag, zero counters.
// ---------------------------------------------------------------------------
__global__ void init_kernel(const float* __restrict__ V,
                            const float* __restrict__ T) {
    const int gtid = blockIdx.x * blockDim.x + threadIdx.x;
    const int row  = gtid >> 5;
    const int lane = gtid & 31;
    if (gtid == 0) { g_vt_sum = 0.0; g_tv_sum = 0.0; g_done = 0u; }
    if (row >= NN) return;

    const float4* v4 = reinterpret_cast<const float4*>(V + (size_t)row * DD);
    const float4* t4 = reinterpret_cast<const float4*>(T + (size_t)row * DD);
    uint2* vh = reinterpret_cast<uint2*>(g_Vhi + (size_t)row * DD);
    uint2* vl = reinterpret_cast<uint2*>(g_Vlo + (size_t)row * DD);
    uint2* th = reinterpret_cast<uint2*>(g_Thi + (size_t)row * DD);
    uint2* tl = reinterpret_cast<uint2*>(g_Tlo + (size_t)row * DD);

    float acc = 0.f;
    #pragma unroll
    for (int p = 0; p < 2; p++) {
        const int idx = lane + p * 32;
        float4 a = v4[idx];
        float4 b = t4[idx];
        acc += a.x * b.x + a.y * b.y + a.z * b.z + a.w * b.w;
        uint2 h, l;
        split4(a, h, l); vh[idx] = h; vl[idx] = l;
        split4(b, h, l); th[idx] = h; tl[idx] = l;
    }
    #pragma unroll
    for (int off = 16; off > 0; off >>= 1)
        acc += __shfl_down_sync(0xFFFFFFFFu, acc, off);
    if (lane == 0) { g_diag[row] = acc; g_cnt[row] = 0; }
}

// ---------------------------------------------------------------------------
// Kernel 2: persistent warp-specialized tcgen05 GEMM + ranking epilogue +
// last-CTA finalize. 148 CTAs x 544 threads.
//   warps 0-15 : epilogue consumers — warp w: TMEM subpartition w&3
//                (rows (w&3)*32+lane), columns [(w>>2)*64, +64)
//   warp 16    : producer (thread 512 issues TMA + MMA)
// TMEM: two 256-col fp32 accumulator buffers, alternating per tile.
// ---------------------------------------------------------------------------
__global__ __launch_bounds__(NTHREADS, 1)
void gemm_tc_kernel(const __grid_constant__ CUtensorMap mVhi,
                    const __grid_constant__ CUtensorMap mVlo,
                    const __grid_constant__ CUtensorMap mThi,
                    const __grid_constant__ CUtensorMap mTlo,
                    const float* __restrict__ V,
                    const float* __restrict__ T,
                    float* __restrict__ out) {
    extern __shared__ char smem_raw[];
    const uint32_t raw  = smem_u32(smem_raw);
    const uint32_t base = (raw + 1023) & ~1023u;
    char* gbase = smem_raw + (base - raw);

    const int tid  = threadIdx.x;
    const int lane = tid & 31;
    const int cta  = blockIdx.x;
    const int ntiles = (NTILES - cta + NCTA - 1) / NCTA;

    float vt = 0.f, tv = 0.f;

#if HAS_TCGEN05
    const int wid = tid >> 5;
    const uint32_t S_TMEMP = base + OFF_TMEMP;
    const uint32_t MB_FULL = base + OFF_MB;        // +0, +8
    const uint32_t MB_EMPT = base + OFF_MB + 16;   // +16, +24
    const uint32_t MB_RES  = base + OFF_MB + 32;   // +32, +40
    const uint32_t MB_EPI  = base + OFF_MB + 48;   // +48, +56
    float* s_mdc = reinterpret_cast<float*>(gbase + OFF_DC);  // 2 x 256 floats

    if (wid == 16) {
        TCGEN05_ALLOC(S_TMEMP, 512);
        TCGEN05_RELINQ();
    }
    if (tid == 0) {
        MBARRIER_INIT(MB_FULL + 0, 1);
        MBARRIER_INIT(MB_FULL + 8, 1);
        MBARRIER_INIT(MB_EMPT + 0, 1);
        MBARRIER_INIT(MB_EMPT + 8, 1);
        MBARRIER_INIT(MB_RES  + 0, 1);
        MBARRIER_INIT(MB_RES  + 8, 1);
        MBARRIER_INIT(MB_EPI  + 0, 16);
        MBARRIER_INIT(MB_EPI  + 8, 16);
    }
    __syncthreads();
    uint32_t tmem;
    asm volatile("ld.shared.b32 %0, [%1];" : "=r"(tmem) : "r"(S_TMEMP));

    if (tid == 512) {
        // ---------------- producer ----------------
        const int nchunks = ntiles * 4;

        auto issue_tma = [&](int kk) {
            const int lt    = kk >> 2;
            const int chunk = kk & 3;
            const int s     = kk & 1;
            const int tile  = cta + lt * NCTA;
            const int row0  = (tile >> 4) * TM;
            const int col0  = (tile & 15) * TN;
            const uint32_t st = base + s * ST_BYTES;
            const uint32_t fb = MB_FULL + s * 8;
            MBARRIER_EXPECT_TX(fb, ST_BYTES);
            tma_ld_2d(st +      0, &mVhi, chunk * 64, row0, fb);
            tma_ld_2d(st + ST_ALO, &mVlo, chunk * 64, row0, fb);
            tma_ld_2d(st + ST_BHI, &mThi, chunk * 64, col0, fb);
            tma_ld_2d(st + ST_BLO, &mTlo, chunk * 64, col0, fb);
        };

        issue_tma(0);
        if (nchunks > 1) issue_tma(1);

        for (int kk = 0; kk < nchunks; kk++) {
            const int s     = kk & 1;
            const int lt    = kk >> 2;
            const int chunk = kk & 3;
            const int buf   = lt & 1;
            const uint32_t st = base + s * ST_BYTES;
            const uint32_t dbuf = tmem + buf * 256;

            MBARRIER_WAIT_PARITY(MB_FULL + s * 8, (kk >> 1) & 1);
            if (chunk == 0 && lt >= 2)
                MBARRIER_WAIT_PARITY(MB_EPI + buf * 8, ((lt - 2) >> 1) & 1);

            const uint64_t dAhi = make_desc(st);
            const uint64_t dAlo = make_desc(st + ST_ALO);
            const uint64_t dBhi = make_desc(st + ST_BHI);
            const uint64_t dBlo = make_desc(st + ST_BLO);
            #pragma unroll
            for (int ks = 0; ks < 4; ks++)
                mma_f16_ss(dbuf, dAhi + ks * 2, dBhi + ks * 2,
                           (chunk == 0 && ks == 0) ? 0u : 1u);
            #pragma unroll
            for (int ks = 0; ks < 4; ks++)
                mma_f16_ss(dbuf, dAhi + ks * 2, dBlo + ks * 2, 1u);
            #pragma unroll
            for (int ks = 0; ks < 4; ks++)
                mma_f16_ss(dbuf, dAlo + ks * 2, dBhi + ks * 2, 1u);

            TCGEN05_COMMIT(MB_EMPT + s * 8);
            if (chunk == 3) TCGEN05_COMMIT(MB_RES + buf * 8);

            if (kk + 2 < nchunks) {
                MBARRIER_WAIT_PARITY(MB_EMPT + s * 8, (kk >> 1) & 1);
                issue_tma(kk + 2);
            }
        }
    } else if (tid < 512) {
        // ---------------- consumers: 16 warps ----------------
        const int w   = wid;          // 0..15
        const int sub = w & 3;        // TMEM subpartition == SMSP
        const int ch  = w >> 2;       // 64-column chunk 0..3
        for (int lt = 0; lt < ntiles; lt++) {
            const int buf  = lt & 1;
            const int tile = cta + lt * NCTA;
            const int row0 = (tile >> 4) * TM;
            const int col0 = (tile & 15) * TN;
            const int r    = row0 + sub * 32 + lane;
            const float dr  = g_diag[r];
            const float mdr = MARGIN - dr;
            const uint32_t dbuf = tmem + buf * 256 + ch * 64;
            float* mdc = s_mdc + buf * 256 + ch * 64;
            int cnt = 0;

            MBARRIER_WAIT_PARITY(MB_RES + buf * 8, (lt >> 1) & 1);
            TCGEN05_FENCE_AFTER();

            // self-written per warp (redundant across subs; each warp reads
            // only what it wrote, so no cross-warp sync needed)
            mdc[lane]      = MARGIN - g_diag[col0 + ch * 64 + lane];
            mdc[lane + 32] = MARGIN - g_diag[col0 + ch * 64 + 32 + lane];

            #pragma unroll 1
            for (int g = 0; g < 2; g++) {
                uint32_t dreg[32];
                TCGEN05_LD_X32(dreg, dbuf + g * 32);
                TCGEN05_WAIT_LD();
                #pragma unroll
                for (int j = 0; j < 32; j++) {
                    const int cc = ch * 64 + g * 32 + j;
                    const int c  = col0 + cc;
                    const float sv = __uint_as_float(dreg[j]);
                    if (c != r) {
                        const float diff = sv - dr;
                        vt += fmaxf(sv + mdr, 0.f);
                        tv += fmaxf(sv + mdc[g * 32 + j], 0.f);
                        if (fabsf(diff) < EPS) {
                            const float4* a4 = reinterpret_cast<const float4*>(V + (size_t)r * DD);
                            const float4* b4 = reinterpret_cast<const float4*>(T + (size_t)c * DD);
                            float e0 = 0.f, e1 = 0.f;
                            #pragma unroll 8
                            for (int k = 0; k < DD / 4; k += 2) {
                                float4 x  = a4[k],     y  = b4[k];
                                float4 x1 = a4[k + 1], y1 = b4[k + 1];
                                e0 += x.x * y.x + x.y * y.y + x.z * y.z + x.w * y.w;
                                e1 += x1.x * y1.x + x1.y * y1.y + x1.z * y1.z + x1.w * y1.w;
                            }
                            cnt += ((e0 + e1) > dr) ? 1 : 0;
                        } else {
                            cnt += (diff > 0.f) ? 1 : 0;
                        }
                    }
                }
            }
            TCGEN05_FENCE_BEFORE();
            if (lane == 0) MBARRIER_ARRIVE(MB_EPI + buf * 8);
            atomicAdd(&g_cnt[r], cnt);
        }
    }

    __syncthreads();
    if (wid == 16) TCGEN05_DEALLOC(tmem, 512);

#else  // ---------------- fallback: plain fp32 (not selected on GB300) -----
    (void)mVhi; (void)mVlo; (void)mThi; (void)mTlo;
    for (int lt = 0; lt < ntiles; lt++) {
        const int tile = cta + lt * NCTA;
        const int row0 = (tile >> 4) * TM;
        const int col0 = (tile & 15) * TN;
        if (tid < 128) {
            const int r = row0 + tid;
            const float dr = g_diag[r];
            const float4* a4 = reinterpret_cast<const float4*>(V + (size_t)r * DD);
            int cnt = 0;
            for (int cc = 0; cc < TN; cc++) {
                const int c = col0 + cc;
                if (c == r) continue;
                const float4* b4 = reinterpret_cast<const float4*>(T + (size_t)c * DD);
                float s = 0.f;
                #pragma unroll 8
                for (int k = 0; k < DD / 4; k++) {
                    float4 x = a4[k], y = b4[k];
                    s += x.x * y.x + x.y * y.y + x.z * y.z + x.w * y.w;
                }
                vt += fmaxf(0.f, MARGIN - dr + s);
                tv += fmaxf(0.f, MARGIN - g_diag[c] + s);
                cnt += (s > dr) ? 1 : 0;
            }
            atomicAdd(&g_cnt[r], cnt);
        }
    }
    __syncthreads();
#endif

    // loss reduction: one double atomic per warp
    #pragma unroll
    for (int off = 16; off > 0; off >>= 1) {
        vt += __shfl_down_sync(0xFFFFFFFFu, vt, off);
        tv += __shfl_down_sync(0xFFFFFFFFu, tv, off);
    }
    if (lane == 0) {
        atomicAdd(&g_vt_sum, (double)vt);
        atomicAdd(&g_tv_sum, (double)tv);
    }

    // ---- last-CTA finalize ----
    __shared__ unsigned s_last;
    __shared__ int rA[512], rB[512], rC[512], rD[512];
    __threadfence();
    __syncthreads();
    if (tid == 0) s_last = (atomicAdd(&g_done, 1u) == (unsigned)(NCTA - 1));
    __syncthreads();
    if (!s_last) return;

    if (tid < 512) {
        int c1 = 0, c5 = 0, c10 = 0, rs = 0;
        for (int i = tid; i < NN; i += 512) {
            int c = g_cnt[i];
            c1  += (c < 1);
            c5  += (c < 5);
            c10 += (c < 10);
            rs  += c;
        }
        rA[tid] = c1; rB[tid] = c5; rC[tid] = c10; rD[tid] = rs;
    }
    __syncthreads();
    for (int s = 256; s > 0; s >>= 1) {
        if (tid < s) {
            rA[tid] += rA[tid + s]; rB[tid] += rB[tid + s];
            rC[tid] += rC[tid + s]; rD[tid] += rD[tid + s];
        }
        __syncthreads();
    }
    if (tid == 0) {
        const double denom = (double)NN * (double)(NN - 1);
        out[0] = (float)(g_vt_sum / denom);
        out[1] = (float)(g_tv_sum / denom);
        out[2] = (float)rA[0] / (float)NN;
        out[3] = (float)rB[0] / (float)NN;
        out[4] = (float)rC[0] / (float)NN;
        out[5] = (float)rD[0] / (float)NN;
    }
}

// ---------------------------------------------------------------------------
typedef CUresult (*EncodeFn)(CUtensorMap*, CUtensorMapDataType, unsigned int,
                             void*, const unsigned long long*,
                             const unsigned long long*, const unsigned int*,
                             const unsigned int*, CUtensorMapInterleave,
                             CUtensorMapSwizzle, CUtensorMapL2promotion,
                             CUtensorMapFloatOOBfill);

static void encode_map(EncodeFn enc, CUtensorMap* m, void* ptr, unsigned rows) {
    unsigned long long dims[2]    = {DD, NN};
    unsigned long long strides[1] = {DD * sizeof(__nv_bfloat16)};
    unsigned int box[2]           = {64, rows};
    unsigned int es[2]            = {1, 1};
    enc(m, CU_TENSOR_MAP_DATA_TYPE_BFLOAT16, 2, ptr, dims, strides, box, es,
        CU_TENSOR_MAP_INTERLEAVE_NONE, CU_TENSOR_MAP_SWIZZLE_128B,
        CU_TENSOR_MAP_L2_PROMOTION_L2_128B, CU_TENSOR_MAP_FLOAT_OOB_FILL_NONE);
}

extern "C" void kernel_launch(void* const* d_in, const int* in_sizes, int n_in,
                              void* d_out, int out_size) {
    (void)in_sizes; (void)n_in; (void)out_size;
    const float* V = (const float*)d_in[0];
    const float* T = (const float*)d_in[1];
    float* out = (float*)d_out;

    void *pVhi, *pVlo, *pThi, *pTlo;
    cudaGetSymbolAddress(&pVhi, g_Vhi);
    cudaGetSymbolAddress(&pVlo, g_Vlo);
    cudaGetSymbolAddress(&pThi, g_Thi);
    cudaGetSymbolAddress(&pTlo, g_Tlo);

    void* sym = nullptr;
    cudaDriverEntryPointQueryResult qr;
    cudaGetDriverEntryPointByVersion("cuTensorMapEncodeTiled", &sym, 12000,
                                     cudaEnableDefault, &qr);
    EncodeFn enc = (EncodeFn)sym;

    CUtensorMap mVhi, mVlo, mThi, mTlo;
    encode_map(enc, &mVhi, pVhi, TM);   // A tiles: 128 rows
    encode_map(enc, &mVlo, pVlo, TM);
    encode_map(enc, &mThi, pThi, TN);   // B tiles: 256 rows
    encode_map(enc, &mTlo, pTlo, TN);

    cudaFuncSetAttribute(gemm_tc_kernel,
                         cudaFuncAttributeMaxDynamicSharedMemorySize, SMEM_DYN);

    init_kernel<<<NN * 32 / 256, 256>>>(V, T);
    gemm_tc_kernel<<<NCTA, NTHREADS, SMEM_DYN>>>(
        mVhi, mVlo, mThi, mTlo, V, T, out);
}

// round 14
// speedup vs baseline: 4.1201x; 1.3287x over previous
#include <cuda_runtime.h>
#include <cuda_bf16.h>
#include <cuda.h>
#include <stdint.h>

#define NN 4096
#define DD 256
#define MARGIN 0.1f
#define EPS 0.002f

#if defined(__CUDA_ARCH_FEAT_SM103_ALL) || defined(__CUDA_ARCH_FEAT_SM100_ALL)
#define HAS_TCGEN05 1
#else
#define HAS_TCGEN05 0
#endif

// idesc kind::f16: dtype=F32, atype=btype=BF16, N=256, M=128 (cg1)
#define IDESC 0x08400490u

// tile geometry
#define TM 128
#define TN 256
#define TILES_X (NN / TN)            // 16
#define TILES_Y (NN / TM)            // 32
#define NTILES  (TILES_X * TILES_Y)  // 512
#define NCTA    148
#define NTHREADS 544                 // 16 consumer warps + 1 producer warp

// stage layout (bytes): Ahi 16K | Alo 16K | Bhi 32K | Blo 32K
#define ST_ALO   16384
#define ST_BHI   32768
#define ST_BLO   65536
#define ST_BYTES 98304
#define OFF_TMEMP  (2 * ST_BYTES)         // 196608
#define OFF_MB     (OFF_TMEMP + 16)       // 8 mbarriers
#define OFF_DC     (OFF_TMEMP + 128)      // 2 x 256 floats
#define SMEM_DYN   (OFF_DC + 2048 + 1024)

typedef unsigned long long u64;

// ---- device-global scratch ----
__device__ double g_vt_sum;
__device__ double g_tv_sum;
__device__ unsigned g_done;
__device__ int    g_cnt[NN];
__device__ float  g_diag[NN];
__device__ __align__(1024) __nv_bfloat16 g_Vhi[NN * DD];
__device__ __align__(1024) __nv_bfloat16 g_Vlo[NN * DD];
__device__ __align__(1024) __nv_bfloat16 g_Thi[NN * DD];
__device__ __align__(1024) __nv_bfloat16 g_Tlo[NN * DD];

// ======================= PTX helpers =======================
__device__ __forceinline__ uint32_t smem_u32(const void* p) {
    uint32_t a;
    asm("{ .reg .u64 t; cvta.to.shared.u64 t, %1; cvt.u32.u64 %0, t; }"
        : "=r"(a) : "l"(p));
    return a;
}

#define MBARRIER_INIT(addr, cnt) \
    asm volatile("mbarrier.init.shared.b64 [%0], %1;" \
        :: "r"((uint32_t)(addr)), "r"((uint32_t)(cnt)) : "memory")

#define MBARRIER_EXPECT_TX(addr, bytes) \
    asm volatile("mbarrier.arrive.expect_tx.shared.b64 _, [%0], %1;" \
        :: "r"((uint32_t)(addr)), "r"((uint32_t)(bytes)) : "memory")

#define MBARRIER_ARRIVE(addr) \
    asm volatile("mbarrier.arrive.shared.b64 _, [%0];" \
        :: "r"((uint32_t)(addr)) : "memory")

#define MBARRIER_WAIT_PARITY(addr, parity) do {                                   \
    uint32_t _mb = (uint32_t)(addr);                                              \
    uint32_t _ph = (uint32_t)(parity);                                            \
    uint32_t _done;                                                               \
    asm volatile("{\n\t.reg .pred p;\n\t"                                         \
        "mbarrier.try_wait.parity.acquire.cta.shared::cta.b64 p, [%1], %2;\n\t"   \
        "selp.b32 %0, 1, 0, p;\n\t}"                                              \
        : "=r"(_done) : "r"(_mb), "r"(_ph) : "memory");                           \
    if (!_done) {                                                                 \
        asm volatile("{\n\t.reg .pred P1;\n\t"                                    \
            "W_%=:\n\t"                                                           \
            "mbarrier.try_wait.parity.acquire.cta.shared::cta.b64 P1, [%0], %1, 0x989680;\n\t" \
            "@P1 bra.uni D_%=;\n\t"                                               \
            "bra.uni W_%=;\n\t"                                                   \
            "D_%=:\n\t}"                                                          \
            :: "r"(_mb), "r"(_ph) : "memory");                                    \
    }                                                                             \
} while (0)

#if HAS_TCGEN05
#define TCGEN05_ALLOC(res_addr, ncols) \
    asm volatile("tcgen05.alloc.cta_group::1.sync.aligned.shared::cta.b32 [%0], %1;" \
        :: "r"((uint32_t)(res_addr)), "r"((uint32_t)(ncols)) : "memory")
#define TCGEN05_RELINQ() \
    asm volatile("tcgen05.relinquish_alloc_permit.cta_group::1.sync.aligned;")
#define TCGEN05_DEALLOC(tmem, ncols) \
    asm volatile("tcgen05.dealloc.cta_group::1.sync.aligned.b32 %0, %1;" \
        :: "r"(tmem), "r"((uint32_t)(ncols)))
#define TCGEN05_COMMIT(mbar) \
    asm volatile("tcgen05.commit.cta_group::1.mbarrier::arrive::one.shared::cluster.b64 [%0];" \
        :: "r"((uint32_t)(mbar)) : "memory")
#define TCGEN05_FENCE_AFTER() \
    asm volatile("tcgen05.fence::after_thread_sync;" ::: "memory")
#define TCGEN05_FENCE_BEFORE() \
    asm volatile("tcgen05.fence::before_thread_sync;" ::: "memory")
#define TCGEN05_WAIT_LD() \
    asm volatile("tcgen05.wait::ld.sync.aligned;" ::: "memory")

#define TCGEN05_LD_X32(r, addr) \
    asm volatile("tcgen05.ld.sync.aligned.32x32b.x32.b32 " \
        "{%0, %1, %2, %3, %4, %5, %6, %7, %8, %9, %10, %11, %12, %13, %14, %15, " \
        " %16, %17, %18, %19, %20, %21, %22, %23, %24, %25, %26, %27, %28, %29, %30, %31}, [%32];" \
        : "=r"((r)[0]),  "=r"((r)[1]),  "=r"((r)[2]),  "=r"((r)[3]),  \
          "=r"((r)[4]),  "=r"((r)[5]),  "=r"((r)[6]),  "=r"((r)[7]),  \
          "=r"((r)[8]),  "=r"((r)[9]),  "=r"((r)[10]), "=r"((r)[11]), \
          "=r"((r)[12]), "=r"((r)[13]), "=r"((r)[14]), "=r"((r)[15]), \
          "=r"((r)[16]), "=r"((r)[17]), "=r"((r)[18]), "=r"((r)[19]), \
          "=r"((r)[20]), "=r"((r)[21]), "=r"((r)[22]), "=r"((r)[23]), \
          "=r"((r)[24]), "=r"((r)[25]), "=r"((r)[26]), "=r"((r)[27]), \
          "=r"((r)[28]), "=r"((r)[29]), "=r"((r)[30]), "=r"((r)[31]) \
        : "r"(addr))

// SW128 SMEM descriptor: layout=SW128(2), version=1, SBO=64, LBO=1
static __device__ __forceinline__ uint64_t make_desc(uint32_t addr) {
    const uint64_t BASE =
        (uint64_t(2)  << 61) | (uint64_t(1) << 46) |
        (uint64_t(64) << 32) | (uint64_t(1) << 16);
    return BASE | ((uint64_t)(addr >> 4) & 0x3FFF);
}

__device__ __forceinline__ void tma_ld_2d(uint32_t dst, const void* map,
                                          int cx, int cy, uint32_t mbar) {
    asm volatile(
        "cp.async.bulk.tensor.2d.shared::cta.global.tile.mbarrier::complete_tx::bytes "
        "[%0], [%1, {%2, %3}], [%4];"
        :: "r"(dst), "l"(map), "r"(cx), "r"(cy), "r"(mbar) : "memory");
}

__device__ __forceinline__ void mma_f16_ss(uint32_t d, uint64_t da, uint64_t db,
                                           uint32_t en) {
    asm volatile("{\n\t.reg .pred p;\n\tsetp.ne.u32 p, %4, 0;\n\t"
        "tcgen05.mma.cta_group::1.kind::f16 [%0], %1, %2, %3, {%5, %5, %5, %5}, p;\n\t}"
        :: "r"(d), "l"(da), "l"(db), "r"(IDESC), "r"(en), "r"(0u) : "memory");
}
#endif  // HAS_TCGEN05

// ---------------------------------------------------------------------------
__device__ __forceinline__ void split4(float4 a, uint2& h, uint2& l) {
    __nv_bfloat162 hxy = __floats2bfloat162_rn(a.x, a.y);
    __nv_bfloat162 hzw = __floats2bfloat162_rn(a.z, a.w);
    float2 fxy = __bfloat1622float2(hxy);
    float2 fzw = __bfloat1622float2(hzw);
    __nv_bfloat162 lxy = __floats2bfloat162_rn(a.x - fxy.x, a.y - fxy.y);
    __nv_bfloat162 lzw = __floats2bfloat162_rn(a.z - fzw.x, a.w - fzw.y);
    h.x = reinterpret_cast<unsigned&>(hxy);
    h.y = reinterpret_cast<unsigned&>(hzw);
    l.x = reinterpret_cast<unsigned&>(lxy);
    l.y = reinterpret_cast<unsigned&>(lzw);
}

// exact fp32 dot of row r of V with row c of T (2-way ILP)
__device__ float exact_dot(const float* __restrict__ V,
                           const float* __restrict__ T, int r, int c) {
    const float4* a4 = reinterpret_cast<const float4*>(V + (size_t)r * DD);
    const float4* b4 = reinterpret_cast<const float4*>(T + (size_t)c * DD);
    float e0 = 0.f, e1 = 0.f;
    #pragma unroll 8
    for (int k = 0; k < DD / 4; k += 2) {
        float4 x  = a4[k],     y  = b4[k];
        float4 x1 = a4[k + 1], y1 = b4[k + 1];
        e0 += x.x * y.x + x.y * y.y + x.z * y.z + x.w * y.w;
        e1 += x1.x * y1.x + x1.y * y1.y + x1.z * y1.z + x1.w * y1.w;
    }
    return e0 + e1;
}

// ---------------------------------------------------------------------------
// Kernel 1: fused init — bf16 hi/lo split, exact fp32 diag, zero counters.
// ---------------------------------------------------------------------------
__global__ void init_kernel(const float* __restrict__ V,
                            const float* __restrict__ T) {
    const int gtid = blockIdx.x * blockDim.x + threadIdx.x;
    const int row  = gtid >> 5;
    const int lane = gtid & 31;
    if (gtid == 0) { g_vt_sum = 0.0; g_tv_sum = 0.0; g_done = 0u; }
    if (row >= NN) return;

    const float4* v4 = reinterpret_cast<const float4*>(V + (size_t)row * DD);
    const float4* t4 = reinterpret_cast<const float4*>(T + (size_t)row * DD);
    uint2* vh = reinterpret_cast<uint2*>(g_Vhi + (size_t)row * DD);
    uint2* vl = reinterpret_cast<uint2*>(g_Vlo + (size_t)row * DD);
    uint2* th = reinterpret_cast<uint2*>(g_Thi + (size_t)row * DD);
    uint2* tl = reinterpret_cast<uint2*>(g_Tlo + (size_t)row * DD);

    float acc = 0.f;
    #pragma unroll
    for (int p = 0; p < 2; p++) {
        const int idx = lane + p * 32;
        float4 a = v4[idx];
        float4 b = t4[idx];
        acc += a.x * b.x + a.y * b.y + a.z * b.z + a.w * b.w;
        uint2 h, l;
        split4(a, h, l); vh[idx] = h; vl[idx] = l;
        split4(b, h, l); th[idx] = h; tl[idx] = l;
    }
    #pragma unroll
    for (int off = 16; off > 0; off >>= 1)
        acc += __shfl_down_sync(0xFFFFFFFFu, acc, off);
    if (lane == 0) { g_diag[row] = acc; g_cnt[row] = 0; }
}

// ---------------------------------------------------------------------------
// Kernel 2: persistent warp-specialized tcgen05 GEMM + ranking epilogue +
// last-CTA finalize. 148 CTAs x 544 threads.
//   warps 0-15 : epilogue consumers — warp w: TMEM subpartition w&3
//                (rows (w&3)*32+lane), columns [(w>>2)*64, +64)
//   warp 16    : producer (thread 512 issues TMA + MMA)
// Epilogue hot loop is branch-free: hinges unconditional (diagonal adds
// exactly MARGIN each direction — subtracted in finalize), rank count via
// diff>EPS, near-ties collected in a per-group bitmask and exact-rechecked
// in one rare branch per 32 elements.
// ---------------------------------------------------------------------------
__global__ __launch_bounds__(NTHREADS, 1)
void gemm_tc_kernel(const __grid_constant__ CUtensorMap mVhi,
                    const __grid_constant__ CUtensorMap mVlo,
                    const __grid_constant__ CUtensorMap mThi,
                    const __grid_constant__ CUtensorMap mTlo,
                    const float* __restrict__ V,
                    const float* __restrict__ T,
                    float* __restrict__ out) {
    extern __shared__ char smem_raw[];
    const uint32_t raw  = smem_u32(smem_raw);
    const uint32_t base = (raw + 1023) & ~1023u;
    char* gbase = smem_raw + (base - raw);

    const int tid  = threadIdx.x;
    const int lane = tid & 31;
    const int cta  = blockIdx.x;
    const int ntiles = (NTILES - cta + NCTA - 1) / NCTA;

    float vt = 0.f, tv = 0.f;

#if HAS_TCGEN05
    const int wid = tid >> 5;
    const uint32_t S_TMEMP = base + OFF_TMEMP;
    const uint32_t MB_FULL = base + OFF_MB;        // +0, +8
    const uint32_t MB_EMPT = base + OFF_MB + 16;   // +16, +24
    const uint32_t MB_RES  = base + OFF_MB + 32;   // +32, +40
    const uint32_t MB_EPI  = base + OFF_MB + 48;   // +48, +56
    float* s_mdc = reinterpret_cast<float*>(gbase + OFF_DC);  // 2 x 256 floats

    if (wid == 16) {
        TCGEN05_ALLOC(S_TMEMP, 512);
        TCGEN05_RELINQ();
    }
    if (tid == 0) {
        MBARRIER_INIT(MB_FULL + 0, 1);
        MBARRIER_INIT(MB_FULL + 8, 1);
        MBARRIER_INIT(MB_EMPT + 0, 1);
        MBARRIER_INIT(MB_EMPT + 8, 1);
        MBARRIER_INIT(MB_RES  + 0, 1);
        MBARRIER_INIT(MB_RES  + 8, 1);
        MBARRIER_INIT(MB_EPI  + 0, 16);
        MBARRIER_INIT(MB_EPI  + 8, 16);
    }
    __syncthreads();
    uint32_t tmem;
    asm volatile("ld.shared.b32 %0, [%1];" : "=r"(tmem) : "r"(S_TMEMP));

    if (tid == 512) {
        // ---------------- producer ----------------
        const int nchunks = ntiles * 4;

        auto issue_tma = [&](int kk) {
            const int lt    = kk >> 2;
            const int chunk = kk & 3;
            const int s     = kk & 1;
            const int tile  = cta + lt * NCTA;
            const int row0  = (tile >> 4) * TM;
            const int col0  = (tile & 15) * TN;
            const uint32_t st = base + s * ST_BYTES;
            const uint32_t fb = MB_FULL + s * 8;
            MBARRIER_EXPECT_TX(fb, ST_BYTES);
            tma_ld_2d(st +      0, &mVhi, chunk * 64, row0, fb);
            tma_ld_2d(st + ST_ALO, &mVlo, chunk * 64, row0, fb);
            tma_ld_2d(st + ST_BHI, &mThi, chunk * 64, col0, fb);
            tma_ld_2d(st + ST_BLO, &mTlo, chunk * 64, col0, fb);
        };

        issue_tma(0);
        if (nchunks > 1) issue_tma(1);

        for (int kk = 0; kk < nchunks; kk++) {
            const int s     = kk & 1;
            const int lt    = kk >> 2;
            const int chunk = kk & 3;
            const int buf   = lt & 1;
            const uint32_t st = base + s * ST_BYTES;
            const uint32_t dbuf = tmem + buf * 256;

            MBARRIER_WAIT_PARITY(MB_FULL + s * 8, (kk >> 1) & 1);
            if (chunk == 0 && lt >= 2)
                MBARRIER_WAIT_PARITY(MB_EPI + buf * 8, ((lt - 2) >> 1) & 1);

            const uint64_t dAhi = make_desc(st);
            const uint64_t dAlo = make_desc(st + ST_ALO);
            const uint64_t dBhi = make_desc(st + ST_BHI);
            const uint64_t dBlo = make_desc(st + ST_BLO);
            #pragma unroll
            for (int ks = 0; ks < 4; ks++)
                mma_f16_ss(dbuf, dAhi + ks * 2, dBhi + ks * 2,
                           (chunk == 0 && ks == 0) ? 0u : 1u);
            #pragma unroll
            for (int ks = 0; ks < 4; ks++)
                mma_f16_ss(dbuf, dAhi + ks * 2, dBlo + ks * 2, 1u);
            #pragma unroll
            for (int ks = 0; ks < 4; ks++)
                mma_f16_ss(dbuf, dAlo + ks * 2, dBhi + ks * 2, 1u);

            TCGEN05_COMMIT(MB_EMPT + s * 8);
            if (chunk == 3) TCGEN05_COMMIT(MB_RES + buf * 8);

            if (kk + 2 < nchunks) {
                MBARRIER_WAIT_PARITY(MB_EMPT + s * 8, (kk >> 1) & 1);
                issue_tma(kk + 2);
            }
        }
    } else if (tid < 512) {
        // ---------------- consumers: 16 warps, branch-free hot loop --------
        const int w   = wid;          // 0..15
        const int sub = w & 3;        // TMEM subpartition == SMSP
        const int ch  = w >> 2;       // 64-column chunk 0..3
        for (int lt = 0; lt < ntiles; lt++) {
            const int buf  = lt & 1;
            const int tile = cta + lt * NCTA;
            const int row0 = (tile >> 4) * TM;
            const int col0 = (tile & 15) * TN;
            const int r    = row0 + sub * 32 + lane;
            const uint32_t dbuf = tmem + buf * 256 + ch * 64;
            float* mdc = s_mdc + buf * 256 + ch * 64;
            int cnt = 0;

            // prefetch diag values BEFORE the result wait (hide LDG latency)
            const float dr  = g_diag[r];
            const float mdr = MARGIN - dr;
            const float m0  = MARGIN - g_diag[col0 + ch * 64 + lane];
            const float m1  = MARGIN - g_diag[col0 + ch * 64 + 32 + lane];

            MBARRIER_WAIT_PARITY(MB_RES + buf * 8, (lt >> 1) & 1);
            TCGEN05_FENCE_AFTER();

            // self-written per warp (each warp reads only what it wrote)
            mdc[lane]      = m0;
            mdc[lane + 32] = m1;

            #pragma unroll 1
            for (int g = 0; g < 2; g++) {
                uint32_t dreg[32];
                TCGEN05_LD_X32(dreg, dbuf + g * 32);
                TCGEN05_WAIT_LD();
                uint32_t tiebits = 0u;
                #pragma unroll
                for (int j = 0; j < 32; j++) {
                    const float sv = __uint_as_float(dreg[j]);
                    const float diff = sv - dr;
                    vt += fmaxf(sv + mdr, 0.f);
                    tv += fmaxf(sv + mdc[g * 32 + j], 0.f);
                    cnt += (diff > EPS) ? 1 : 0;
                    tiebits |= (fabsf(diff) <= EPS) ? (1u << j) : 0u;
                }
                if (tiebits) {   // rare: diagonal element + true near-ties
                    do {
                        const int j = __ffs(tiebits) - 1;
                        tiebits &= tiebits - 1u;
                        const int c = col0 + ch * 64 + g * 32 + j;
                        if (c != r)
                            cnt += (exact_dot(V, T, r, c) > dr) ? 1 : 0;
                    } while (tiebits);
                }
            }
            TCGEN05_FENCE_BEFORE();
            if (lane == 0) MBARRIER_ARRIVE(MB_EPI + buf * 8);
            atomicAdd(&g_cnt[r], cnt);
        }
    }

    __syncthreads();
    if (wid == 16) TCGEN05_DEALLOC(tmem, 512);

#else  // ---------------- fallback: plain fp32 (not selected on GB300) -----
    (void)mVhi; (void)mVlo; (void)mThi; (void)mTlo;
    for (int lt = 0; lt < ntiles; lt++) {
        const int tile = cta + lt * NCTA;
        const int row0 = (tile >> 4) * TM;
        const int col0 = (tile & 15) * TN;
        if (tid < 128) {
            const int r = row0 + tid;
            const float dr = g_diag[r];
            int cnt = 0;
            for (int cc = 0; cc < TN; cc++) {
                const int c = col0 + cc;
                if (c == r) { vt += MARGIN; tv += MARGIN; continue; }
                float s = exact_dot(V, T, r, c);
                vt += fmaxf(0.f, MARGIN - dr + s);
                tv += fmaxf(0.f, MARGIN - g_diag[c] + s);
                cnt += (s > dr) ? 1 : 0;
            }
            atomicAdd(&g_cnt[r], cnt);
        }
    }
    __syncthreads();
#endif

    // loss reduction: one double atomic per warp
    #pragma unroll
    for (int off = 16; off > 0; off >>= 1) {
        vt += __shfl_down_sync(0xFFFFFFFFu, vt, off);
        tv += __shfl_down_sync(0xFFFFFFFFu, tv, off);
    }
    if (lane == 0) {
        atomicAdd(&g_vt_sum, (double)vt);
        atomicAdd(&g_tv_sum, (double)tv);
    }

    // ---- last-CTA finalize ----
    __shared__ unsigned s_last;
    __shared__ int rA[512], rB[512], rC[512], rD[512];
    __threadfence();
    __syncthreads();
    if (tid == 0) s_last = (atomicAdd(&g_done, 1u) == (unsigned)(NCTA - 1));
    __syncthreads();
    if (!s_last) return;

    if (tid < 512) {
        int c1 = 0, c5 = 0, c10 = 0, rs = 0;
        for (int i = tid; i < NN; i += 512) {
            int c = g_cnt[i];
            c1  += (c < 1);
            c5  += (c < 5);
            c10 += (c < 10);
            rs  += c;
        }
        rA[tid] = c1; rB[tid] = c5; rC[tid] = c10; rD[tid] = rs;
    }
    __syncthreads();
    for (int s = 256; s > 0; s >>= 1) {
        if (tid < s) {
            rA[tid] += rA[tid + s]; rB[tid] += rB[tid + s];
            rC[tid] += rC[tid + s]; rD[tid] += rD[tid + s];
        }
        __syncthreads();
    }
    if (tid == 0) {
        const double denom = (double)NN * (double)(NN - 1);
        const double diagfix = (double)NN * (double)MARGIN;  // diagonal hinge
        out[0] = (float)((g_vt_sum - diagfix) / denom);
        out[1] = (float)((g_tv_sum - diagfix) / denom);
        out[2] = (float)rA[0] / (float)NN;
        out[3] = (float)rB[0] / (float)NN;
        out[4] = (float)rC[0] / (float)NN;
        out[5] = (float)rD[0] / (float)NN;
    }
}

// ---------------------------------------------------------------------------
typedef CUresult (*EncodeFn)(CUtensorMap*, CUtensorMapDataType, unsigned int,
                             void*, const unsigned long long*,
                             const unsigned long long*, const unsigned int*,
                             const unsigned int*, CUtensorMapInterleave,
                             CUtensorMapSwizzle, CUtensorMapL2promotion,
                             CUtensorMapFloatOOBfill);

static void encode_map(EncodeFn enc, CUtensorMap* m, void* ptr, unsigned rows) {
    unsigned long long dims[2]    = {DD, NN};
    unsigned long long strides[1] = {DD * sizeof(__nv_bfloat16)};
    unsigned int box[2]           = {64, rows};
    unsigned int es[2]            = {1, 1};
    enc(m, CU_TENSOR_MAP_DATA_TYPE_BFLOAT16, 2, ptr, dims, strides, box, es,
        CU_TENSOR_MAP_INTERLEAVE_NONE, CU_TENSOR_MAP_SWIZZLE_128B,
        CU_TENSOR_MAP_L2_PROMOTION_L2_128B, CU_TENSOR_MAP_FLOAT_OOB_FILL_NONE);
}

extern "C" void kernel_launch(void* const* d_in, const int* in_sizes, int n_in,
                              void* d_out, int out_size) {
    (void)in_sizes; (void)n_in; (void)out_size;
    const float* V = (const float*)d_in[0];
    const float* T = (const float*)d_in[1];
    float* out = (float*)d_out;

    void *pVhi, *pVlo, *pThi, *pTlo;
    cudaGetSymbolAddress(&pVhi, g_Vhi);
    cudaGetSymbolAddress(&pVlo, g_Vlo);
    cudaGetSymbolAddress(&pThi, g_Thi);
    cudaGetSymbolAddress(&pTlo, g_Tlo);

    void* sym = nullptr;
    cudaDriverEntryPointQueryResult qr;
    cudaGetDriverEntryPointByVersion("cuTensorMapEncodeTiled", &sym, 12000,
                                     cudaEnableDefault, &qr);
    EncodeFn enc = (EncodeFn)sym;

    CUtensorMap mVhi, mVlo, mThi, mTlo;
    encode_map(enc, &mVhi, pVhi, TM);   // A tiles: 128 rows
    encode_map(enc, &mVlo, pVlo, TM);
    encode_map(enc, &mThi, pThi, TN);   // B tiles: 256 rows
    encode_map(enc, &mTlo, pTlo, TN);

    cudaFuncSetAttribute(gemm_tc_kernel,
                         cudaFuncAttributeMaxDynamicSharedMemorySize, SMEM_DYN);

    init_kernel<<<NN * 32 / 256, 256>>>(V, T);
    gemm_tc_kernel<<<NCTA, NTHREADS, SMEM_DYN>>>(
        mVhi, mVlo, mThi, mTlo, V, T, out);
}